// round 11
// baseline (speedup 1.0000x reference)
#include <cuda_runtime.h>
#include <cuda_fp16.h>

#define NCODES 4096
#define DIM 64
#define NPTS 65536
#define NTIL 32
#define TILE_B 8704          // 8192 B int8 frags + 512 Caug(s32)
#define XSCL (127.0f / 6.0f)
#define CSCL (127.0f / 5.5f)
#define UQ ((12.0f / 127.0f) * (5.5f / 127.0f))
#define MARGIN_INT 986       // ~4.0 distance units + s16-floor slack
#define DECAY_F 0.99f
#define OMD_F 0.01f
#define EPS_F 1e-5f

__device__ float g_counts[NCODES];
__device__ float g_embed[NCODES * DIM];
__device__ float g_ncs[NCODES];
__device__ float g_factor[NCODES];
__device__ float g_csq[NCODES];
__device__ __align__(16) unsigned char g_cbB[NTIL * TILE_B];

#define OFF_B    0             // 2 x 8704 = 17408
#define OFF_TM   17408         // [pt128][t32 pad 33][c4] u32 (2 x s16) = 67584
#define OFF_PMIN 84992         // 128 s32
#define SMEM_TOTAL 85504

static __device__ __forceinline__ void mma_s8(int* c, const unsigned* a,
                                              unsigned b0, unsigned b1) {
    asm("mma.sync.aligned.m16n8k32.row.col.s32.s8.s8.s32 "
        "{%0,%1,%2,%3}, {%4,%5,%6,%7}, {%8,%9}, {%0,%1,%2,%3};"
        : "+r"(c[0]), "+r"(c[1]), "+r"(c[2]), "+r"(c[3])
        : "r"(a[0]), "r"(a[1]), "r"(a[2]), "r"(a[3]), "r"(b0), "r"(b1));
}
static __device__ __forceinline__ void cp16(unsigned dst, const void* src) {
    asm volatile("cp.async.cg.shared.global [%0], [%1], 16;" :: "r"(dst), "l"(src));
}
#define CP_COMMIT() asm volatile("cp.async.commit_group;" ::: "memory")
#define CP_WAIT1()  asm volatile("cp.async.wait_group 1;" ::: "memory")

static __device__ __forceinline__ unsigned q4(float4 v, float s) {
    int q0 = __float2int_rn(fminf(fmaxf(v.x * s, -127.f), 127.f));
    int q1 = __float2int_rn(fminf(fmaxf(v.y * s, -127.f), 127.f));
    int q2 = __float2int_rn(fminf(fmaxf(v.z * s, -127.f), 127.f));
    int q3 = __float2int_rn(fminf(fmaxf(v.w * s, -127.f), 127.f));
    return (q0 & 255) | ((q1 & 255) << 8) | ((q2 & 255) << 16) | ((q3 & 255) << 24);
}

// ---- prep: B int8 frags = q(-c); Caug blob; csq f32; zero scratch ----
// B frag m16n8k32: element (n,d): s=d>>5, nt=n>>3, np=nt>>1, half=nt&1,
// lane=(n&7)*4+((d>>2)&3), reg=(d&31)>>4, byte=d&3
__global__ void prep_kernel(const float* __restrict__ codebook) {
    int i = blockIdx.x * blockDim.x + threadIdx.x;
    if (i >= NCODES * DIM) return;
    int k = i >> 6, d = i & 63;
    int tile = k >> 7, n = k & 127;
    int q = __float2int_rn(fminf(fmaxf(-codebook[i] * CSCL, -127.f), 127.f));
    int s = d >> 5, nt = n >> 3;
    unsigned off = (unsigned)tile * TILE_B +
                   (((s * 8 + (nt >> 1)) * 32 + ((n & 7) * 4 + ((d >> 2) & 3))) * 16) +
                   (nt & 1) * 8 + ((d & 31) >> 4) * 4 + (d & 3);
    g_cbB[off] = (unsigned char)(q & 255);
    g_embed[i] = 0.0f;
    if (d == 0) {
        const float* row = codebook + (size_t)k * DIM;
        float sum = 0.0f;
#pragma unroll
        for (int j = 0; j < DIM; j++) sum += row[j] * row[j];
        g_csq[k] = sum;
        g_counts[k] = 0.0f;
        // Caug s32: [nt][col8] at tile offset 8192
        *(int*)(g_cbB + (unsigned)tile * TILE_B + 8192 + (nt * 8 + (n & 7)) * 4) =
            __float2int_rn(sum / UQ);
    }
}

// ---- main: 8 warps, m16n128/warp, 128 pts/CTA, 2 CTAs/SM ----
__global__ void __launch_bounds__(256, 2) vq_kernel(
    const float* __restrict__ x, const float* __restrict__ codebook,
    float* __restrict__ o_quant, float* __restrict__ o_idx) {
    extern __shared__ char smem[];
    const int tid = threadIdx.x, lane = tid & 31, w = tid >> 5;
    const int r0 = lane >> 2, c4 = lane & 3;

    // A int8 fragments (rows w*16 + r0, +8), 2 k-steps
    unsigned afr[2][4];
    {
        const float* xr0 = x + ((size_t)blockIdx.x * 128 + w * 16 + r0) * DIM;
        const float* xr1 = xr0 + 8 * DIM;
#pragma unroll
        for (int s = 0; s < 2; s++) {
            afr[s][0] = q4(*(const float4*)(xr0 + s * 32 + c4 * 4), XSCL);
            afr[s][1] = q4(*(const float4*)(xr1 + s * 32 + c4 * 4), XSCL);
            afr[s][2] = q4(*(const float4*)(xr0 + s * 32 + 16 + c4 * 4), XSCL);
            afr[s][3] = q4(*(const float4*)(xr1 + s * 32 + 16 + c4 * 4), XSCL);
        }
    }

    const unsigned smem_b = (unsigned)__cvta_generic_to_shared(smem + OFF_B);
#pragma unroll
    for (int t = 0; t < 2; t++) {
        const unsigned char* src = g_cbB + (size_t)t * TILE_B;
        for (int c = tid; c < TILE_B / 16; c += 256)
            cp16(smem_b + t * TILE_B + c * 16, src + c * 16);
        CP_COMMIT();
    }

    int gm[2] = {0x7FFFFFFF, 0x7FFFFFFF};
    unsigned* tm = (unsigned*)(smem + OFF_TM);

    for (int t = 0; t < NTIL; ++t) {
        const int buf = t & 1;
        CP_WAIT1();
        __syncthreads();

        const uint4* B4 = (const uint4*)(smem + OFF_B + buf * TILE_B);
        const int2* ca = (const int2*)(smem + OFF_B + buf * TILE_B + 8192);

        int acc[64];  // [nt16][c0 c1 c2 c3]
#pragma unroll
        for (int nt = 0; nt < 16; nt++) {
            int2 cv = ca[nt * 4 + c4];  // Caug for cols 2c4, 2c4+1
            acc[nt * 4 + 0] = cv.x;
            acc[nt * 4 + 1] = cv.y;
            acc[nt * 4 + 2] = cv.x;
            acc[nt * 4 + 3] = cv.y;
        }
#pragma unroll
        for (int s = 0; s < 2; s++)
#pragma unroll
            for (int np = 0; np < 8; np++) {
                uint4 b = B4[(s * 8 + np) * 32 + lane];
                mma_s8(&acc[(np * 2 + 0) * 4], afr[s], b.x, b.y);
                mma_s8(&acc[(np * 2 + 1) * 4], afr[s], b.z, b.w);
            }

        // epilogue: s32 min trees per (slot, col-half)
#pragma unroll
        for (int slot = 0; slot < 2; slot++) {
            int m0 = acc[slot * 2 + 0], m1 = acc[slot * 2 + 1];
#pragma unroll
            for (int nt = 1; nt < 16; nt++) {
                m0 = min(m0, acc[nt * 4 + slot * 2 + 0]);
                m1 = min(m1, acc[nt * 4 + slot * 2 + 1]);
            }
            gm[slot] = min(gm[slot], min(m0, m1));
            unsigned tv = ((unsigned)(unsigned short)(short)(m0 >> 3)) |
                          ((unsigned)(unsigned short)(short)(m1 >> 3) << 16);
            const int pt = w * 16 + slot * 8 + r0;
            tm[(pt * 33 + t) * 4 + c4] = tv;
        }

        __syncthreads();
        if (t + 2 < NTIL) {
            const unsigned char* src = g_cbB + (size_t)(t + 2) * TILE_B;
            for (int c = tid; c < TILE_B / 16; c += 256)
                cp16(smem_b + buf * TILE_B + c * 16, src + c * 16);
        }
        CP_COMMIT();
    }

    // per-point exact-int min
    int* pminS = (int*)(smem + OFF_PMIN);
#pragma unroll
    for (int s = 0; s < 2; s++) {
        int g = gm[s];
        g = min(g, __shfl_xor_sync(0xffffffffu, g, 1));
        g = min(g, __shfl_xor_sync(0xffffffffu, g, 2));
        if (c4 == 0) pminS[w * 16 + s * 8 + r0] = g;
    }
    __syncwarp();

    // recovery + exact fp32 refine, warp per point
    const uint4* tm4 = (const uint4*)tm;
    for (int ii = 0; ii < 16; ii++) {
        const int pl = w * 16 + ii;
        const int gpt = blockIdx.x * 128 + pl;
        const int th = pminS[pl] + MARGIN_INT;

        float2 xv2 = ((const float2*)(x + (size_t)gpt * DIM))[lane];
        float xsq = fmaf(xv2.x, xv2.x, xv2.y * xv2.y);
#pragma unroll
        for (int o = 1; o <= 16; o <<= 1) xsq += __shfl_xor_sync(0xffffffffu, xsq, o);

        uint4 e = tm4[pl * 33 + lane];  // tile = lane; 8 s16 subset mins
        unsigned m8 = 0;
        if (((int)(short)(e.x & 0xFFFF) << 3) < th) m8 |= 1u;
        if (((int)(short)(e.x >> 16) << 3) < th) m8 |= 2u;
        if (((int)(short)(e.y & 0xFFFF) << 3) < th) m8 |= 4u;
        if (((int)(short)(e.y >> 16) << 3) < th) m8 |= 8u;
        if (((int)(short)(e.z & 0xFFFF) << 3) < th) m8 |= 16u;
        if (((int)(short)(e.z >> 16) << 3) < th) m8 |= 32u;
        if (((int)(short)(e.w & 0xFFFF) << 3) < th) m8 |= 64u;
        if (((int)(short)(e.w >> 16) << 3) < th) m8 |= 128u;

        float bd = 3.4e38f;
        int bi = 0x7FFFFFFF;
        unsigned hitb = __ballot_sync(0xffffffffu, m8 != 0);
        while (hitb) {
            const int src = __ffs(hitb) - 1;
            hitb &= hitb - 1;
            unsigned m = __shfl_sync(0xffffffffu, m8, src);
            for (int bit = 0; bit < 8; bit++) {
                if (!(m & (1u << bit))) continue;
                const int code = src * 128 + (lane >> 1) * 8 + (bit >> 1) * 2 + (bit & 1);
                const int part = lane & 1;
                const float4* xr = (const float4*)(x + (size_t)gpt * DIM) + part * 8;
                const float4* cr = (const float4*)(codebook + (size_t)code * DIM) + part * 8;
                float dot = 0.0f;
#pragma unroll
                for (int j = 0; j < 8; j++) {
                    float4 xa = xr[j], cc = cr[j];
                    dot = fmaf(xa.x, cc.x, dot);
                    dot = fmaf(xa.y, cc.y, dot);
                    dot = fmaf(xa.z, cc.z, dot);
                    dot = fmaf(xa.w, cc.w, dot);
                }
                dot += __shfl_xor_sync(0xffffffffu, dot, 1);
                float dd = fmaf(-2.0f, dot, xsq) + g_csq[code];
                int wi = code;
#pragma unroll
                for (int o = 2; o <= 16; o <<= 1) {
                    float od = __shfl_xor_sync(0xffffffffu, dd, o);
                    int oi = __shfl_xor_sync(0xffffffffu, wi, o);
                    if (od < dd || (od == dd && oi < wi)) { dd = od; wi = oi; }
                }
                if (dd < bd || (dd == bd && wi < bi)) { bd = dd; bi = wi; }
            }
        }

        if (lane == 0) o_idx[gpt] = (float)bi;
        ((float2*)(o_quant + (size_t)gpt * DIM))[lane] =
            ((const float2*)(codebook + (size_t)bi * DIM))[lane];
        if (lane == 0) atomicAdd(&g_counts[bi], 1.0f);
        atomicAdd(&g_embed[(size_t)bi * DIM + 2 * lane], xv2.x);
        atomicAdd(&g_embed[(size_t)bi * DIM + 2 * lane + 1], xv2.y);
    }
}

__global__ void finalize1_kernel(const float* __restrict__ cluster_size,
                                 float* __restrict__ o_cs) {
    __shared__ float warpsum[32];
    __shared__ float s_n;
    float local = 0.0f;
    for (int k = threadIdx.x; k < NCODES; k += blockDim.x) {
        float ncs = DECAY_F * cluster_size[k] + OMD_F * g_counts[k];
        o_cs[k] = ncs;
        g_ncs[k] = ncs;
        local += ncs;
    }
#pragma unroll
    for (int o = 16; o; o >>= 1) local += __shfl_down_sync(0xffffffffu, local, o);
    if ((threadIdx.x & 31) == 0) warpsum[threadIdx.x >> 5] = local;
    __syncthreads();
    if (threadIdx.x < 32) {
        float v = (threadIdx.x < (blockDim.x >> 5)) ? warpsum[threadIdx.x] : 0.0f;
#pragma unroll
        for (int o = 16; o; o >>= 1) v += __shfl_down_sync(0xffffffffu, v, o);
        if (threadIdx.x == 0) s_n = v;
    }
    __syncthreads();
    float n = s_n;
    float denom = n + (float)NCODES * EPS_F;
    for (int k = threadIdx.x; k < NCODES; k += blockDim.x) {
        float sm = (g_ncs[k] + EPS_F) / denom * n;
        g_factor[k] = 1.0f / sm;
    }
}

__global__ void finalize2_kernel(const float* __restrict__ ema_w,
                                 float* __restrict__ o_cb,
                                 float* __restrict__ o_ema) {
    int i = blockIdx.x * blockDim.x + threadIdx.x;
    if (i >= NCODES * DIM) return;
    float e = DECAY_F * ema_w[i] + OMD_F * g_embed[i];
    o_ema[i] = e;
    o_cb[i] = e * g_factor[i >> 6];
}

extern "C" void kernel_launch(void* const* d_in, const int* in_sizes, int n_in,
                              void* d_out, int out_size) {
    const float* x            = (const float*)d_in[0];
    const float* codebook     = (const float*)d_in[1];
    const float* cluster_size = (const float*)d_in[2];
    const float* ema_w        = (const float*)d_in[3];

    float* out     = (float*)d_out;
    float* o_quant = out;
    float* o_idx   = o_quant + (size_t)NPTS * DIM;
    float* o_cb    = o_idx + NPTS;
    float* o_cs    = o_cb + (size_t)NCODES * DIM;
    float* o_ema   = o_cs + NCODES;

    static int smem_set = 0;
    if (!smem_set) {
        cudaFuncSetAttribute(vq_kernel, cudaFuncAttributeMaxDynamicSharedMemorySize, SMEM_TOTAL);
        smem_set = 1;
    }

    prep_kernel<<<(NCODES * DIM + 255) / 256, 256>>>(codebook);
    vq_kernel<<<NPTS / 128, 256, SMEM_TOTAL>>>(x, codebook, o_quant, o_idx);
    finalize1_kernel<<<1, 1024>>>(cluster_size, o_cs);
    finalize2_kernel<<<(NCODES * DIM + 255) / 256, 256>>>(ema_w, o_cb, o_ema);
}

// round 13
// speedup vs baseline: 1.8509x; 1.8509x over previous
#include <cuda_runtime.h>
#include <cuda_fp16.h>

#define NCODES 4096
#define DIM 64
#define NPTS 65536
#define NTIL 32
#define TILE_B 16640        // 128 codes x 64 k x fp16 + 256B csq-h2
#define MARGIN 1.25f
#define DECAY_F 0.99f
#define OMD_F 0.01f
#define EPS_F 1e-5f

__device__ float g_counts[NCODES];
__device__ float g_embed[NCODES * DIM];
__device__ float g_ncs[NCODES];
__device__ float g_factor[NCODES];
__device__ float g_csq[NCODES];
__device__ __align__(16) unsigned char g_cbB[NTIL * TILE_B];

#define OFF_B    0             // 2 x 16640 = 33280
#define OFF_TM   33280         // [pt128][t32 pad33] x 8 fp16 = 67584
#define OFF_PM0  100864        // 128 f32 (col-half 0 partial min)
#define OFF_PM1  101376        // 128 f32 (col-half 1 partial min)
#define SMEM_TOTAL 101888

static __device__ __forceinline__ unsigned hmin2u(unsigned a, unsigned b) {
    __half2 r = __hmin2(*(__half2*)&a, *(__half2*)&b);
    return *(unsigned*)&r;
}
static __device__ __forceinline__ unsigned hadd2u(unsigned a, unsigned b) {
    __half2 r = __hadd2(*(__half2*)&a, *(__half2*)&b);
    return *(unsigned*)&r;
}
static __device__ __forceinline__ unsigned packh2(float lo, float hi) {
    __half2 h = __floats2half2_rn(lo, hi);
    return *(unsigned*)&h;
}
static __device__ __forceinline__ float h2lo(unsigned u) { return __low2float(*(__half2*)&u); }
static __device__ __forceinline__ float h2hi(unsigned u) { return __high2float(*(__half2*)&u); }

static __device__ __forceinline__ void mmaA(unsigned& d0, unsigned& d1,
                                            const unsigned* a, unsigned b0, unsigned b1) {
    asm("mma.sync.aligned.m16n8k16.row.col.f16.f16.f16.f16 "
        "{%0,%1}, {%2,%3,%4,%5}, {%6,%7}, {%0,%1};"
        : "+r"(d0), "+r"(d1)
        : "r"(a[0]), "r"(a[1]), "r"(a[2]), "r"(a[3]), "r"(b0), "r"(b1));
}
static __device__ __forceinline__ void mmaZ(unsigned& d0, unsigned& d1,
                                            const unsigned* a, unsigned b0, unsigned b1) {
    asm("mma.sync.aligned.m16n8k16.row.col.f16.f16.f16.f16 "
        "{%0,%1}, {%2,%3,%4,%5}, {%6,%7}, {%8,%8};"
        : "=r"(d0), "=r"(d1)
        : "r"(a[0]), "r"(a[1]), "r"(a[2]), "r"(a[3]), "r"(b0), "r"(b1), "r"(0u));
}
static __device__ __forceinline__ void cp16(unsigned dst, const void* src) {
    asm volatile("cp.async.cg.shared.global [%0], [%1], 16;" :: "r"(dst), "l"(src));
}
#define CP_COMMIT() asm volatile("cp.async.commit_group;" ::: "memory")
#define CP_WAIT1()  asm volatile("cp.async.wait_group 1;" ::: "memory")

// B-fragment offset (layout validated R4..R9), ks 0..3
static __device__ __forceinline__ unsigned bfrag_off(int tile, int n, int ks, int c) {
    int nt = n >> 3, nn = n & 7;
    return (unsigned)tile * TILE_B +
           (((ks * 8 + (nt >> 1)) * 32 + (nn * 4 + ((c & 7) >> 1))) * 16) +
           (nt & 1) * 8 + (c >> 3) * 4 + (c & 1) * 2;
}

// ---- prep: B frags fp16(-2c); csq-h2 blob per tile; csq f32; zero scratch ----
__global__ void prep_kernel(const float* __restrict__ codebook) {
    int i = blockIdx.x * blockDim.x + threadIdx.x;
    if (i >= NCODES * DIM) return;
    int k = i >> 6, d = i & 63;
    int tile = k >> 7, n = k & 127;
    *(__half*)(g_cbB + bfrag_off(tile, n, d >> 4, d & 15)) =
        __float2half_rn(-2.0f * codebook[i]);
    g_embed[i] = 0.0f;
    if (d == 0) {
        const float* row = codebook + (size_t)k * DIM;
        float s = 0.0f;
#pragma unroll
        for (int j = 0; j < DIM; j++) s += row[j] * row[j];
        g_csq[k] = s;
        g_counts[k] = 0.0f;
        int nt = n >> 3, c4 = (n & 7) >> 1, half = n & 1;
        *(__half*)(g_cbB + (unsigned)tile * TILE_B + 16384 +
                   ((nt * 4 + c4) * 4) + half * 2) = __float2half_rn(s);
    }
}

// ---- main: 8 warps (4 row x 2 col), m32n64 per warp, 128 pts/CTA, 2 CTAs/SM ----
__global__ void __launch_bounds__(256, 2) vq_kernel(
    const float* __restrict__ x, const float* __restrict__ codebook,
    float* __restrict__ o_quant, float* __restrict__ o_idx) {
    extern __shared__ char smem[];
    const int tid = threadIdx.x, lane = tid & 31, w = tid >> 5;
    const int rw = w >> 1, cw = w & 1;  // row-warp (32 pts), col-warp (64 codes)
    const int r0 = lane >> 2, c4 = lane & 3;

    // A fragments: 2 m-tiles (rows rw*32 + mt*16 + r0, +8)
    unsigned afr[2][4][4];
#pragma unroll
    for (int mt = 0; mt < 2; mt++) {
        const float* xr0 = x + ((size_t)blockIdx.x * 128 + rw * 32 + mt * 16 + r0) * DIM;
        const float* xr1 = xr0 + 8 * DIM;
#pragma unroll
        for (int ks = 0; ks < 4; ks++) {
            float2 a = *(const float2*)(xr0 + ks * 16 + 2 * c4);
            float2 b = *(const float2*)(xr1 + ks * 16 + 2 * c4);
            float2 c = *(const float2*)(xr0 + ks * 16 + 8 + 2 * c4);
            float2 d = *(const float2*)(xr1 + ks * 16 + 8 + 2 * c4);
            afr[mt][ks][0] = packh2(a.x, a.y);
            afr[mt][ks][1] = packh2(b.x, b.y);
            afr[mt][ks][2] = packh2(c.x, c.y);
            afr[mt][ks][3] = packh2(d.x, d.y);
        }
    }

    const unsigned smem_b = (unsigned)__cvta_generic_to_shared(smem + OFF_B);
#pragma unroll
    for (int t = 0; t < 2; t++) {
        const unsigned char* src = g_cbB + (size_t)t * TILE_B;
        for (int c = tid; c < TILE_B / 16; c += 256)
            cp16(smem_b + t * TILE_B + c * 16, src + c * 16);
        CP_COMMIT();
    }

    unsigned gmin[4] = {0x7BFF7BFFu, 0x7BFF7BFFu, 0x7BFF7BFFu, 0x7BFF7BFFu};
    __half* tmh = (__half*)(smem + OFF_TM);

    for (int t = 0; t < NTIL; ++t) {
        const int buf = t & 1;
        CP_WAIT1();
        __syncthreads();

        const uint4* B4 = (const uint4*)(smem + OFF_B + buf * TILE_B);
        const unsigned* csq2 = (const unsigned*)(smem + OFF_B + buf * TILE_B + 16384);

        unsigned acc[2][16];  // [mt][i*2+slot], i = p*2+X, cols cw*64-rel
#pragma unroll
        for (int ks = 0; ks < 4; ks++)
#pragma unroll
            for (int p = 0; p < 4; p++) {
                uint4 b = B4[(ks * 8 + cw * 4 + p) * 32 + lane];
                if (ks == 0) {
#pragma unroll
                    for (int mt = 0; mt < 2; mt++) {
                        mmaZ(acc[mt][(p * 2 + 0) * 2], acc[mt][(p * 2 + 0) * 2 + 1],
                             afr[mt][0], b.x, b.y);
                        mmaZ(acc[mt][(p * 2 + 1) * 2], acc[mt][(p * 2 + 1) * 2 + 1],
                             afr[mt][0], b.z, b.w);
                    }
                } else {
#pragma unroll
                    for (int mt = 0; mt < 2; mt++) {
                        mmaA(acc[mt][(p * 2 + 0) * 2], acc[mt][(p * 2 + 0) * 2 + 1],
                             afr[mt][ks], b.x, b.y);
                        mmaA(acc[mt][(p * 2 + 1) * 2], acc[mt][(p * 2 + 1) * 2 + 1],
                             afr[mt][ks], b.z, b.w);
                    }
                }
            }

        // epilogue: add csq, hmin trees; subset = 16 codes {cw*64+j*8+2c4+h}
        unsigned cq[8];
#pragma unroll
        for (int j = 0; j < 8; j++) cq[j] = csq2[(cw * 8 + j) * 4 + c4];

#pragma unroll
        for (int mt = 0; mt < 2; mt++)
#pragma unroll
            for (int slot = 0; slot < 2; slot++) {
                unsigned m[4];
#pragma unroll
                for (int j = 0; j < 4; j++)
                    m[j] = hmin2u(hadd2u(acc[mt][(j + 0) * 2 + slot], cq[j]),
                                  hadd2u(acc[mt][(j + 4) * 2 + slot], cq[j + 4]));
                unsigned tv = hmin2u(hmin2u(m[0], m[1]), hmin2u(m[2], m[3]));
                gmin[mt * 2 + slot] = hmin2u(gmin[mt * 2 + slot], tv);
                const int pt = rw * 32 + mt * 16 + slot * 8 + r0;
                tmh[(pt * 33 + t) * 8 + cw * 4 + c4] =
                    __hmin(*(__half*)&tv, *((__half*)&tv + 1));
            }

        __syncthreads();  // ALL warps done reading buf before overwrite (fixes R12 race)
        if (t + 2 < NTIL) {
            const unsigned char* src = g_cbB + (size_t)(t + 2) * TILE_B;
            for (int c = tid; c < TILE_B / 16; c += 256)
                cp16(smem_b + buf * TILE_B + c * 16, src + c * 16);
        }
        CP_COMMIT();
    }

    // per-point partial min (this warp's 64 cols)
    float* pm = (float*)(smem + (cw ? OFF_PM1 : OFF_PM0));
#pragma unroll
    for (int s = 0; s < 4; s++) {
        unsigned g = gmin[s];
        g = hmin2u(g, __shfl_xor_sync(0xffffffffu, g, 1));
        g = hmin2u(g, __shfl_xor_sync(0xffffffffu, g, 2));
        if (c4 == 0)
            pm[rw * 32 + (s >> 1) * 16 + (s & 1) * 8 + r0] = fminf(h2lo(g), h2hi(g));
    }
    __syncthreads();

    // recovery + exact refine, warp per point (16 points per warp)
    const float* pm0 = (const float*)(smem + OFF_PM0);
    const float* pm1 = (const float*)(smem + OFF_PM1);
    const uint4* tm4 = (const uint4*)(smem + OFF_TM);
    for (int ii = 0; ii < 16; ii++) {
        const int pl = w * 16 + ii;
        const int gpt = blockIdx.x * 128 + pl;
        const float th = fminf(pm0[pl], pm1[pl]) + MARGIN;

        float2 xv2 = ((const float2*)(x + (size_t)gpt * DIM))[lane];
        float xsq = fmaf(xv2.x, xv2.x, xv2.y * xv2.y);
#pragma unroll
        for (int o = 1; o <= 16; o <<= 1) xsq += __shfl_xor_sync(0xffffffffu, xsq, o);

        uint4 e = tm4[pl * 33 + lane];  // tile = lane; 8 fp16 subset mins
        unsigned m8 = 0;
        if (h2lo(e.x) < th) m8 |= 1u;
        if (h2hi(e.x) < th) m8 |= 2u;
        if (h2lo(e.y) < th) m8 |= 4u;
        if (h2hi(e.y) < th) m8 |= 8u;
        if (h2lo(e.z) < th) m8 |= 16u;
        if (h2hi(e.z) < th) m8 |= 32u;
        if (h2lo(e.w) < th) m8 |= 64u;
        if (h2hi(e.w) < th) m8 |= 128u;

        float bd = 3.4e38f;
        int bi = 0x7FFFFFFF;
        unsigned hitb = __ballot_sync(0xffffffffu, m8 != 0);
        while (hitb) {
            const int src = __ffs(hitb) - 1;
            hitb &= hitb - 1;
            unsigned m = __shfl_sync(0xffffffffu, m8, src);
            for (int sh = 0; sh < 8; sh++) {
                if (!(m & (1u << sh))) continue;
                // subset sh = colhalf*4 + c4s: codes src*128 + colhalf*64 + j*8 + 2*c4s + h
                const int code = src * 128 + (sh >> 2) * 64 + (lane >> 2) * 8 +
                                 2 * (sh & 3) + ((lane >> 1) & 1);
                const int part = lane & 1;
                const float4* xr = (const float4*)(x + (size_t)gpt * DIM) + part * 8;
                const float4* cr = (const float4*)(codebook + (size_t)code * DIM) + part * 8;
                float dot = 0.0f;
#pragma unroll
                for (int j = 0; j < 8; j++) {
                    float4 xa = xr[j], ca = cr[j];
                    dot = fmaf(xa.x, ca.x, dot);
                    dot = fmaf(xa.y, ca.y, dot);
                    dot = fmaf(xa.z, ca.z, dot);
                    dot = fmaf(xa.w, ca.w, dot);
                }
                dot += __shfl_xor_sync(0xffffffffu, dot, 1);
                float dd = fmaf(-2.0f, dot, xsq) + g_csq[code];
                int wi = code;
#pragma unroll
                for (int o = 2; o <= 16; o <<= 1) {
                    float od = __shfl_xor_sync(0xffffffffu, dd, o);
                    int oi = __shfl_xor_sync(0xffffffffu, wi, o);
                    if (od < dd || (od == dd && oi < wi)) { dd = od; wi = oi; }
                }
                if (dd < bd || (dd == bd && wi < bi)) { bd = dd; bi = wi; }
            }
        }

        if (lane == 0) o_idx[gpt] = (float)bi;
        ((float2*)(o_quant + (size_t)gpt * DIM))[lane] =
            ((const float2*)(codebook + (size_t)bi * DIM))[lane];
        if (lane == 0) atomicAdd(&g_counts[bi], 1.0f);
        atomicAdd(&g_embed[(size_t)bi * DIM + 2 * lane], xv2.x);
        atomicAdd(&g_embed[(size_t)bi * DIM + 2 * lane + 1], xv2.y);
    }
}

__global__ void finalize1_kernel(const float* __restrict__ cluster_size,
                                 float* __restrict__ o_cs) {
    __shared__ float warpsum[32];
    __shared__ float s_n;
    float local = 0.0f;
    for (int k = threadIdx.x; k < NCODES; k += blockDim.x) {
        float ncs = DECAY_F * cluster_size[k] + OMD_F * g_counts[k];
        o_cs[k] = ncs;
        g_ncs[k] = ncs;
        local += ncs;
    }
#pragma unroll
    for (int o = 16; o; o >>= 1) local += __shfl_down_sync(0xffffffffu, local, o);
    if ((threadIdx.x & 31) == 0) warpsum[threadIdx.x >> 5] = local;
    __syncthreads();
    if (threadIdx.x < 32) {
        float v = (threadIdx.x < (blockDim.x >> 5)) ? warpsum[threadIdx.x] : 0.0f;
#pragma unroll
        for (int o = 16; o; o >>= 1) v += __shfl_down_sync(0xffffffffu, v, o);
        if (threadIdx.x == 0) s_n = v;
    }
    __syncthreads();
    float n = s_n;
    float denom = n + (float)NCODES * EPS_F;
    for (int k = threadIdx.x; k < NCODES; k += blockDim.x) {
        float sm = (g_ncs[k] + EPS_F) / denom * n;
        g_factor[k] = 1.0f / sm;
    }
}

__global__ void finalize2_kernel(const float* __restrict__ ema_w,
                                 float* __restrict__ o_cb,
                                 float* __restrict__ o_ema) {
    int i = blockIdx.x * blockDim.x + threadIdx.x;
    if (i >= NCODES * DIM) return;
    float e = DECAY_F * ema_w[i] + OMD_F * g_embed[i];
    o_ema[i] = e;
    o_cb[i] = e * g_factor[i >> 6];
}

extern "C" void kernel_launch(void* const* d_in, const int* in_sizes, int n_in,
                              void* d_out, int out_size) {
    const float* x            = (const float*)d_in[0];
    const float* codebook     = (const float*)d_in[1];
    const float* cluster_size = (const float*)d_in[2];
    const float* ema_w        = (const float*)d_in[3];

    float* out     = (float*)d_out;
    float* o_quant = out;
    float* o_idx   = o_quant + (size_t)NPTS * DIM;
    float* o_cb    = o_idx + NPTS;
    float* o_cs    = o_cb + (size_t)NCODES * DIM;
    float* o_ema   = o_cs + NCODES;

    static int smem_set = 0;
    if (!smem_set) {
        cudaFuncSetAttribute(vq_kernel, cudaFuncAttributeMaxDynamicSharedMemorySize, SMEM_TOTAL);
        smem_set = 1;
    }

    prep_kernel<<<(NCODES * DIM + 255) / 256, 256>>>(codebook);
    vq_kernel<<<NPTS / 128, 256, SMEM_TOTAL>>>(x, codebook, o_quant, o_idx);
    finalize1_kernel<<<1, 1024>>>(cluster_size, o_cs);
    finalize2_kernel<<<(NCODES * DIM + 255) / 256, 256>>>(ema_w, o_cb, o_ema);
}

// round 14
// speedup vs baseline: 1.9931x; 1.0768x over previous
#include <cuda_runtime.h>
#include <cuda_fp16.h>

#define NCODES 4096
#define DIM 64
#define NPTS 65536
#define NTIL 32
#define TILE_B 16640        // 128 codes x 64 k x fp16 + 256B csq-h2
#define MARGIN 1.25f
#define PTS 64              // points per CTA
#define DECAY_F 0.99f
#define OMD_F 0.01f
#define EPS_F 1e-5f

__device__ float g_counts[NCODES];
__device__ float g_embed[NCODES * DIM];
__device__ float g_ncs[NCODES];
__device__ float g_factor[NCODES];
__device__ float g_csq[NCODES];
__device__ __align__(16) unsigned char g_cbB[NTIL * TILE_B];

#define OFF_B    0             // 2 x 16640 = 33280
#define OFF_TM   33280         // [pt64][t32 pad33] x 8 fp16 = 33792
#define OFF_PM0  67072         // 64 f32 (col-half 0 partial min)
#define OFF_PM1  67328         // 64 f32 (col-half 1 partial min)
#define SMEM_TOTAL 67584

static __device__ __forceinline__ unsigned hmin2u(unsigned a, unsigned b) {
    __half2 r = __hmin2(*(__half2*)&a, *(__half2*)&b);
    return *(unsigned*)&r;
}
static __device__ __forceinline__ unsigned hadd2u(unsigned a, unsigned b) {
    __half2 r = __hadd2(*(__half2*)&a, *(__half2*)&b);
    return *(unsigned*)&r;
}
static __device__ __forceinline__ unsigned packh2(float lo, float hi) {
    __half2 h = __floats2half2_rn(lo, hi);
    return *(unsigned*)&h;
}
static __device__ __forceinline__ float h2lo(unsigned u) { return __low2float(*(__half2*)&u); }
static __device__ __forceinline__ float h2hi(unsigned u) { return __high2float(*(__half2*)&u); }

static __device__ __forceinline__ void mmaA(unsigned& d0, unsigned& d1,
                                            const unsigned* a, unsigned b0, unsigned b1) {
    asm("mma.sync.aligned.m16n8k16.row.col.f16.f16.f16.f16 "
        "{%0,%1}, {%2,%3,%4,%5}, {%6,%7}, {%0,%1};"
        : "+r"(d0), "+r"(d1)
        : "r"(a[0]), "r"(a[1]), "r"(a[2]), "r"(a[3]), "r"(b0), "r"(b1));
}
static __device__ __forceinline__ void mmaZ(unsigned& d0, unsigned& d1,
                                            const unsigned* a, unsigned b0, unsigned b1) {
    asm("mma.sync.aligned.m16n8k16.row.col.f16.f16.f16.f16 "
        "{%0,%1}, {%2,%3,%4,%5}, {%6,%7}, {%8,%8};"
        : "=r"(d0), "=r"(d1)
        : "r"(a[0]), "r"(a[1]), "r"(a[2]), "r"(a[3]), "r"(b0), "r"(b1), "r"(0u));
}
static __device__ __forceinline__ void cp16(unsigned dst, const void* src) {
    asm volatile("cp.async.cg.shared.global [%0], [%1], 16;" :: "r"(dst), "l"(src));
}
#define CP_COMMIT() asm volatile("cp.async.commit_group;" ::: "memory")
#define CP_WAIT1()  asm volatile("cp.async.wait_group 1;" ::: "memory")

// B-fragment offset (layout validated R4..R13), ks 0..3
static __device__ __forceinline__ unsigned bfrag_off(int tile, int n, int ks, int c) {
    int nt = n >> 3, nn = n & 7;
    return (unsigned)tile * TILE_B +
           (((ks * 8 + (nt >> 1)) * 32 + (nn * 4 + ((c & 7) >> 1))) * 16) +
           (nt & 1) * 8 + (c >> 3) * 4 + (c & 1) * 2;
}

// ---- prep: B frags fp16(-2c); csq-h2 blob per tile; csq f32; zero scratch ----
__global__ void prep_kernel(const float* __restrict__ codebook) {
    int i = blockIdx.x * blockDim.x + threadIdx.x;
    if (i >= NCODES * DIM) return;
    int k = i >> 6, d = i & 63;
    int tile = k >> 7, n = k & 127;
    *(__half*)(g_cbB + bfrag_off(tile, n, d >> 4, d & 15)) =
        __float2half_rn(-2.0f * codebook[i]);
    g_embed[i] = 0.0f;
    if (d == 0) {
        const float* row = codebook + (size_t)k * DIM;
        float s = 0.0f;
#pragma unroll
        for (int j = 0; j < DIM; j++) s += row[j] * row[j];
        g_csq[k] = s;
        g_counts[k] = 0.0f;
        int nt = n >> 3, c4 = (n & 7) >> 1, half = n & 1;
        *(__half*)(g_cbB + (unsigned)tile * TILE_B + 16384 +
                   ((nt * 4 + c4) * 4) + half * 2) = __float2half_rn(s);
    }
}

// ---- main: 4 warps (2 row x 2 col), m32n64 per warp, 64 pts/CTA, 3 CTAs/SM ----
__global__ void __launch_bounds__(128, 3) vq_kernel(
    const float* __restrict__ x, const float* __restrict__ codebook,
    float* __restrict__ o_quant, float* __restrict__ o_idx) {
    extern __shared__ char smem[];
    const int tid = threadIdx.x, lane = tid & 31, w = tid >> 5;
    const int rw = w >> 1, cw = w & 1;  // row-warp (32 pts), col-warp (64 codes)
    const int r0 = lane >> 2, c4 = lane & 3;

    // A fragments: 2 m-tiles (rows rw*32 + mt*16 + r0, +8)
    unsigned afr[2][4][4];
#pragma unroll
    for (int mt = 0; mt < 2; mt++) {
        const float* xr0 = x + ((size_t)blockIdx.x * PTS + rw * 32 + mt * 16 + r0) * DIM;
        const float* xr1 = xr0 + 8 * DIM;
#pragma unroll
        for (int ks = 0; ks < 4; ks++) {
            float2 a = *(const float2*)(xr0 + ks * 16 + 2 * c4);
            float2 b = *(const float2*)(xr1 + ks * 16 + 2 * c4);
            float2 c = *(const float2*)(xr0 + ks * 16 + 8 + 2 * c4);
            float2 d = *(const float2*)(xr1 + ks * 16 + 8 + 2 * c4);
            afr[mt][ks][0] = packh2(a.x, a.y);
            afr[mt][ks][1] = packh2(b.x, b.y);
            afr[mt][ks][2] = packh2(c.x, c.y);
            afr[mt][ks][3] = packh2(d.x, d.y);
        }
    }

    const unsigned smem_b = (unsigned)__cvta_generic_to_shared(smem + OFF_B);
#pragma unroll
    for (int t = 0; t < 2; t++) {
        const unsigned char* src = g_cbB + (size_t)t * TILE_B;
        for (int c = tid; c < TILE_B / 16; c += 128)
            cp16(smem_b + t * TILE_B + c * 16, src + c * 16);
        CP_COMMIT();
    }

    unsigned gmin[4] = {0x7BFF7BFFu, 0x7BFF7BFFu, 0x7BFF7BFFu, 0x7BFF7BFFu};
    __half* tmh = (__half*)(smem + OFF_TM);

    for (int t = 0; t < NTIL; ++t) {
        const int buf = t & 1;
        CP_WAIT1();
        __syncthreads();

        const uint4* B4 = (const uint4*)(smem + OFF_B + buf * TILE_B);
        const unsigned* csq2 = (const unsigned*)(smem + OFF_B + buf * TILE_B + 16384);

        unsigned acc[2][16];  // [mt][i*2+slot], i = p*2+X, cols cw*64-rel
#pragma unroll
        for (int ks = 0; ks < 4; ks++)
#pragma unroll
            for (int p = 0; p < 4; p++) {
                uint4 b = B4[(ks * 8 + cw * 4 + p) * 32 + lane];
                if (ks == 0) {
#pragma unroll
                    for (int mt = 0; mt < 2; mt++) {
                        mmaZ(acc[mt][(p * 2 + 0) * 2], acc[mt][(p * 2 + 0) * 2 + 1],
                             afr[mt][0], b.x, b.y);
                        mmaZ(acc[mt][(p * 2 + 1) * 2], acc[mt][(p * 2 + 1) * 2 + 1],
                             afr[mt][0], b.z, b.w);
                    }
                } else {
#pragma unroll
                    for (int mt = 0; mt < 2; mt++) {
                        mmaA(acc[mt][(p * 2 + 0) * 2], acc[mt][(p * 2 + 0) * 2 + 1],
                             afr[mt][ks], b.x, b.y);
                        mmaA(acc[mt][(p * 2 + 1) * 2], acc[mt][(p * 2 + 1) * 2 + 1],
                             afr[mt][ks], b.z, b.w);
                    }
                }
            }

        // epilogue: add csq, hmin trees; subset = 16 codes {cw*64+j*8+2c4+h}
        unsigned cq[8];
#pragma unroll
        for (int j = 0; j < 8; j++) cq[j] = csq2[(cw * 8 + j) * 4 + c4];

#pragma unroll
        for (int mt = 0; mt < 2; mt++)
#pragma unroll
            for (int slot = 0; slot < 2; slot++) {
                unsigned m[4];
#pragma unroll
                for (int j = 0; j < 4; j++)
                    m[j] = hmin2u(hadd2u(acc[mt][(j + 0) * 2 + slot], cq[j]),
                                  hadd2u(acc[mt][(j + 4) * 2 + slot], cq[j + 4]));
                unsigned tv = hmin2u(hmin2u(m[0], m[1]), hmin2u(m[2], m[3]));
                gmin[mt * 2 + slot] = hmin2u(gmin[mt * 2 + slot], tv);
                const int pt = rw * 32 + mt * 16 + slot * 8 + r0;
                tmh[(pt * 33 + t) * 8 + cw * 4 + c4] =
                    __hmin(*(__half*)&tv, *((__half*)&tv + 1));
            }

        __syncthreads();  // all warps done reading buf before overwrite
        if (t + 2 < NTIL) {
            const unsigned char* src = g_cbB + (size_t)(t + 2) * TILE_B;
            for (int c = tid; c < TILE_B / 16; c += 128)
                cp16(smem_b + buf * TILE_B + c * 16, src + c * 16);
        }
        CP_COMMIT();
    }

    // per-point partial min (this warp's 64 cols)
    float* pm = (float*)(smem + (cw ? OFF_PM1 : OFF_PM0));
#pragma unroll
    for (int s = 0; s < 4; s++) {
        unsigned g = gmin[s];
        g = hmin2u(g, __shfl_xor_sync(0xffffffffu, g, 1));
        g = hmin2u(g, __shfl_xor_sync(0xffffffffu, g, 2));
        if (c4 == 0)
            pm[rw * 32 + (s >> 1) * 16 + (s & 1) * 8 + r0] = fminf(h2lo(g), h2hi(g));
    }
    __syncthreads();

    // recovery + exact refine, warp per point (16 points per warp)
    const float* pm0 = (const float*)(smem + OFF_PM0);
    const float* pm1 = (const float*)(smem + OFF_PM1);
    const uint4* tm4 = (const uint4*)(smem + OFF_TM);
    for (int ii = 0; ii < 16; ii++) {
        const int pl = w * 16 + ii;
        const int gpt = blockIdx.x * PTS + pl;
        const float th = fminf(pm0[pl], pm1[pl]) + MARGIN;

        float2 xv2 = ((const float2*)(x + (size_t)gpt * DIM))[lane];
        float xsq = fmaf(xv2.x, xv2.x, xv2.y * xv2.y);
#pragma unroll
        for (int o = 1; o <= 16; o <<= 1) xsq += __shfl_xor_sync(0xffffffffu, xsq, o);

        uint4 e = tm4[pl * 33 + lane];  // tile = lane; 8 fp16 subset mins
        unsigned m8 = 0;
        if (h2lo(e.x) < th) m8 |= 1u;
        if (h2hi(e.x) < th) m8 |= 2u;
        if (h2lo(e.y) < th) m8 |= 4u;
        if (h2hi(e.y) < th) m8 |= 8u;
        if (h2lo(e.z) < th) m8 |= 16u;
        if (h2hi(e.z) < th) m8 |= 32u;
        if (h2lo(e.w) < th) m8 |= 64u;
        if (h2hi(e.w) < th) m8 |= 128u;

        float bd = 3.4e38f;
        int bi = 0x7FFFFFFF;
        unsigned hitb = __ballot_sync(0xffffffffu, m8 != 0);
        while (hitb) {
            const int src = __ffs(hitb) - 1;
            hitb &= hitb - 1;
            unsigned m = __shfl_sync(0xffffffffu, m8, src);
            for (int sh = 0; sh < 8; sh++) {
                if (!(m & (1u << sh))) continue;
                // subset sh = colhalf*4 + c4s: codes src*128 + colhalf*64 + j*8 + 2*c4s + h
                const int code = src * 128 + (sh >> 2) * 64 + (lane >> 2) * 8 +
                                 2 * (sh & 3) + ((lane >> 1) & 1);
                const int part = lane & 1;
                const float4* xr = (const float4*)(x + (size_t)gpt * DIM) + part * 8;
                const float4* cr = (const float4*)(codebook + (size_t)code * DIM) + part * 8;
                float dot = 0.0f;
#pragma unroll
                for (int j = 0; j < 8; j++) {
                    float4 xa = xr[j], ca = cr[j];
                    dot = fmaf(xa.x, ca.x, dot);
                    dot = fmaf(xa.y, ca.y, dot);
                    dot = fmaf(xa.z, ca.z, dot);
                    dot = fmaf(xa.w, ca.w, dot);
                }
                dot += __shfl_xor_sync(0xffffffffu, dot, 1);
                float dd = fmaf(-2.0f, dot, xsq) + g_csq[code];
                int wi = code;
#pragma unroll
                for (int o = 2; o <= 16; o <<= 1) {
                    float od = __shfl_xor_sync(0xffffffffu, dd, o);
                    int oi = __shfl_xor_sync(0xffffffffu, wi, o);
                    if (od < dd || (od == dd && oi < wi)) { dd = od; wi = oi; }
                }
                if (dd < bd || (dd == bd && wi < bi)) { bd = dd; bi = wi; }
            }
        }

        if (lane == 0) o_idx[gpt] = (float)bi;
        ((float2*)(o_quant + (size_t)gpt * DIM))[lane] =
            ((const float2*)(codebook + (size_t)bi * DIM))[lane];
        if (lane == 0) atomicAdd(&g_counts[bi], 1.0f);
        atomicAdd(&g_embed[(size_t)bi * DIM + 2 * lane], xv2.x);
        atomicAdd(&g_embed[(size_t)bi * DIM + 2 * lane + 1], xv2.y);
    }
}

__global__ void finalize1_kernel(const float* __restrict__ cluster_size,
                                 float* __restrict__ o_cs) {
    __shared__ float warpsum[32];
    __shared__ float s_n;
    float local = 0.0f;
    for (int k = threadIdx.x; k < NCODES; k += blockDim.x) {
        float ncs = DECAY_F * cluster_size[k] + OMD_F * g_counts[k];
        o_cs[k] = ncs;
        g_ncs[k] = ncs;
        local += ncs;
    }
#pragma unroll
    for (int o = 16; o; o >>= 1) local += __shfl_down_sync(0xffffffffu, local, o);
    if ((threadIdx.x & 31) == 0) warpsum[threadIdx.x >> 5] = local;
    __syncthreads();
    if (threadIdx.x < 32) {
        float v = (threadIdx.x < (blockDim.x >> 5)) ? warpsum[threadIdx.x] : 0.0f;
#pragma unroll
        for (int o = 16; o; o >>= 1) v += __shfl_down_sync(0xffffffffu, v, o);
        if (threadIdx.x == 0) s_n = v;
    }
    __syncthreads();
    float n = s_n;
    float denom = n + (float)NCODES * EPS_F;
    for (int k = threadIdx.x; k < NCODES; k += blockDim.x) {
        float sm = (g_ncs[k] + EPS_F) / denom * n;
        g_factor[k] = 1.0f / sm;
    }
}

__global__ void finalize2_kernel(const float* __restrict__ ema_w,
                                 float* __restrict__ o_cb,
                                 float* __restrict__ o_ema) {
    int i = blockIdx.x * blockDim.x + threadIdx.x;
    if (i >= NCODES * DIM) return;
    float e = DECAY_F * ema_w[i] + OMD_F * g_embed[i];
    o_ema[i] = e;
    o_cb[i] = e * g_factor[i >> 6];
}

extern "C" void kernel_launch(void* const* d_in, const int* in_sizes, int n_in,
                              void* d_out, int out_size) {
    const float* x            = (const float*)d_in[0];
    const float* codebook     = (const float*)d_in[1];
    const float* cluster_size = (const float*)d_in[2];
    const float* ema_w        = (const float*)d_in[3];

    float* out     = (float*)d_out;
    float* o_quant = out;
    float* o_idx   = o_quant + (size_t)NPTS * DIM;
    float* o_cb    = o_idx + NPTS;
    float* o_cs    = o_cb + (size_t)NCODES * DIM;
    float* o_ema   = o_cs + NCODES;

    static int smem_set = 0;
    if (!smem_set) {
        cudaFuncSetAttribute(vq_kernel, cudaFuncAttributeMaxDynamicSharedMemorySize, SMEM_TOTAL);
        smem_set = 1;
    }

    prep_kernel<<<(NCODES * DIM + 255) / 256, 256>>>(codebook);
    vq_kernel<<<NPTS / PTS, 128, SMEM_TOTAL>>>(x, codebook, o_quant, o_idx);
    finalize1_kernel<<<1, 1024>>>(cluster_size, o_cs);
    finalize2_kernel<<<(NCODES * DIM + 255) / 256, 256>>>(ema_w, o_cb, o_ema);
}

// round 15
// speedup vs baseline: 2.0855x; 1.0464x over previous
#include <cuda_runtime.h>
#include <cuda_fp16.h>

#define NCODES 4096
#define DIM 64
#define NPTS 65536
#define NTIL 32
#define TILE_B 16640        // 128 codes x 64 k x fp16 + 256B csq-h2
#define MARGIN 0.9f
#define PTS 64              // points per CTA
#define DECAY_F 0.99f
#define OMD_F 0.01f
#define EPS_F 1e-5f

__device__ float g_counts[NCODES];
__device__ float g_embed[NCODES * DIM];
__device__ float g_ncs[NCODES];
__device__ float g_factor[NCODES];
__device__ float g_csq[NCODES];
__device__ __align__(16) unsigned char g_cbB[NTIL * TILE_B];

#define OFF_B    0             // 2 x 16640 = 33280
#define OFF_TM   33280         // [pt64][t32 pad33] x 8 fp16 = 33792
#define OFF_PM0  67072         // 64 f32 (col-half 0 partial min)
#define OFF_PM1  67328         // 64 f32 (col-half 1 partial min)
#define SMEM_TOTAL 67584

static __device__ __forceinline__ unsigned hmin2u(unsigned a, unsigned b) {
    __half2 r = __hmin2(*(__half2*)&a, *(__half2*)&b);
    return *(unsigned*)&r;
}
static __device__ __forceinline__ unsigned hadd2u(unsigned a, unsigned b) {
    __half2 r = __hadd2(*(__half2*)&a, *(__half2*)&b);
    return *(unsigned*)&r;
}
static __device__ __forceinline__ unsigned packh2(float lo, float hi) {
    __half2 h = __floats2half2_rn(lo, hi);
    return *(unsigned*)&h;
}
static __device__ __forceinline__ float h2lo(unsigned u) { return __low2float(*(__half2*)&u); }
static __device__ __forceinline__ float h2hi(unsigned u) { return __high2float(*(__half2*)&u); }

static __device__ __forceinline__ void mmaA(unsigned& d0, unsigned& d1,
                                            const unsigned* a, unsigned b0, unsigned b1) {
    asm("mma.sync.aligned.m16n8k16.row.col.f16.f16.f16.f16 "
        "{%0,%1}, {%2,%3,%4,%5}, {%6,%7}, {%0,%1};"
        : "+r"(d0), "+r"(d1)
        : "r"(a[0]), "r"(a[1]), "r"(a[2]), "r"(a[3]), "r"(b0), "r"(b1));
}
static __device__ __forceinline__ void mmaZ(unsigned& d0, unsigned& d1,
                                            const unsigned* a, unsigned b0, unsigned b1) {
    asm("mma.sync.aligned.m16n8k16.row.col.f16.f16.f16.f16 "
        "{%0,%1}, {%2,%3,%4,%5}, {%6,%7}, {%8,%8};"
        : "=r"(d0), "=r"(d1)
        : "r"(a[0]), "r"(a[1]), "r"(a[2]), "r"(a[3]), "r"(b0), "r"(b1), "r"(0u));
}
static __device__ __forceinline__ void cp16(unsigned dst, const void* src) {
    asm volatile("cp.async.cg.shared.global [%0], [%1], 16;" :: "r"(dst), "l"(src));
}
#define CP_COMMIT() asm volatile("cp.async.commit_group;" ::: "memory")
#define CP_WAIT1()  asm volatile("cp.async.wait_group 1;" ::: "memory")

// B-fragment offset (layout validated R4..R14), ks 0..3
static __device__ __forceinline__ unsigned bfrag_off(int tile, int n, int ks, int c) {
    int nt = n >> 3, nn = n & 7;
    return (unsigned)tile * TILE_B +
           (((ks * 8 + (nt >> 1)) * 32 + (nn * 4 + ((c & 7) >> 1))) * 16) +
           (nt & 1) * 8 + (c >> 3) * 4 + (c & 1) * 2;
}

// ---- prep: B frags fp16(-2c); csq-h2 blob per tile; csq f32; zero scratch ----
__global__ void prep_kernel(const float* __restrict__ codebook) {
    int i = blockIdx.x * blockDim.x + threadIdx.x;
    if (i >= NCODES * DIM) return;
    int k = i >> 6, d = i & 63;
    int tile = k >> 7, n = k & 127;
    *(__half*)(g_cbB + bfrag_off(tile, n, d >> 4, d & 15)) =
        __float2half_rn(-2.0f * codebook[i]);
    g_embed[i] = 0.0f;
    if (d == 0) {
        const float* row = codebook + (size_t)k * DIM;
        float s = 0.0f;
#pragma unroll
        for (int j = 0; j < DIM; j++) s += row[j] * row[j];
        g_csq[k] = s;
        g_counts[k] = 0.0f;
        int nt = n >> 3, c4 = (n & 7) >> 1, half = n & 1;
        *(__half*)(g_cbB + (unsigned)tile * TILE_B + 16384 +
                   ((nt * 4 + c4) * 4) + half * 2) = __float2half_rn(s);
    }
}

// ---- main: 4 warps (2 row x 2 col), m32n64 per warp, 64 pts/CTA, 3 CTAs/SM ----
__global__ void __launch_bounds__(128, 3) vq_kernel(
    const float* __restrict__ x, const float* __restrict__ codebook,
    float* __restrict__ o_quant, float* __restrict__ o_idx) {
    extern __shared__ char smem[];
    const int tid = threadIdx.x, lane = tid & 31, w = tid >> 5;
    const int rw = w >> 1, cw = w & 1;  // row-warp (32 pts), col-warp (64 codes)
    const int r0 = lane >> 2, c4 = lane & 3;

    // A fragments: 2 m-tiles (rows rw*32 + mt*16 + r0, +8)
    unsigned afr[2][4][4];
#pragma unroll
    for (int mt = 0; mt < 2; mt++) {
        const float* xr0 = x + ((size_t)blockIdx.x * PTS + rw * 32 + mt * 16 + r0) * DIM;
        const float* xr1 = xr0 + 8 * DIM;
#pragma unroll
        for (int ks = 0; ks < 4; ks++) {
            float2 a = *(const float2*)(xr0 + ks * 16 + 2 * c4);
            float2 b = *(const float2*)(xr1 + ks * 16 + 2 * c4);
            float2 c = *(const float2*)(xr0 + ks * 16 + 8 + 2 * c4);
            float2 d = *(const float2*)(xr1 + ks * 16 + 8 + 2 * c4);
            afr[mt][ks][0] = packh2(a.x, a.y);
            afr[mt][ks][1] = packh2(b.x, b.y);
            afr[mt][ks][2] = packh2(c.x, c.y);
            afr[mt][ks][3] = packh2(d.x, d.y);
        }
    }

    const unsigned smem_b = (unsigned)__cvta_generic_to_shared(smem + OFF_B);
#pragma unroll
    for (int t = 0; t < 2; t++) {
        const unsigned char* src = g_cbB + (size_t)t * TILE_B;
        for (int c = tid; c < TILE_B / 16; c += 128)
            cp16(smem_b + t * TILE_B + c * 16, src + c * 16);
        CP_COMMIT();
    }

    unsigned gmin[4] = {0x7BFF7BFFu, 0x7BFF7BFFu, 0x7BFF7BFFu, 0x7BFF7BFFu};
    __half* tmh = (__half*)(smem + OFF_TM);

    for (int t = 0; t < NTIL; ++t) {
        const int buf = t & 1;
        CP_WAIT1();
        __syncthreads();

        const uint4* B4 = (const uint4*)(smem + OFF_B + buf * TILE_B);
        const unsigned* csq2 = (const unsigned*)(smem + OFF_B + buf * TILE_B + 16384);

        unsigned acc[2][16];  // [mt][i*2+slot], i = p*2+X, cols cw*64-rel
#pragma unroll
        for (int ks = 0; ks < 4; ks++)
#pragma unroll
            for (int p = 0; p < 4; p++) {
                uint4 b = B4[(ks * 8 + cw * 4 + p) * 32 + lane];
                if (ks == 0) {
#pragma unroll
                    for (int mt = 0; mt < 2; mt++) {
                        mmaZ(acc[mt][(p * 2 + 0) * 2], acc[mt][(p * 2 + 0) * 2 + 1],
                             afr[mt][0], b.x, b.y);
                        mmaZ(acc[mt][(p * 2 + 1) * 2], acc[mt][(p * 2 + 1) * 2 + 1],
                             afr[mt][0], b.z, b.w);
                    }
                } else {
#pragma unroll
                    for (int mt = 0; mt < 2; mt++) {
                        mmaA(acc[mt][(p * 2 + 0) * 2], acc[mt][(p * 2 + 0) * 2 + 1],
                             afr[mt][ks], b.x, b.y);
                        mmaA(acc[mt][(p * 2 + 1) * 2], acc[mt][(p * 2 + 1) * 2 + 1],
                             afr[mt][ks], b.z, b.w);
                    }
                }
            }

        // epilogue: add csq, hmin trees; subset = 16 codes {cw*64+j*8+2c4+h}
        unsigned cq[8];
#pragma unroll
        for (int j = 0; j < 8; j++) cq[j] = csq2[(cw * 8 + j) * 4 + c4];

#pragma unroll
        for (int mt = 0; mt < 2; mt++)
#pragma unroll
            for (int slot = 0; slot < 2; slot++) {
                unsigned m[4];
#pragma unroll
                for (int j = 0; j < 4; j++)
                    m[j] = hmin2u(hadd2u(acc[mt][(j + 0) * 2 + slot], cq[j]),
                                  hadd2u(acc[mt][(j + 4) * 2 + slot], cq[j + 4]));
                unsigned tv = hmin2u(hmin2u(m[0], m[1]), hmin2u(m[2], m[3]));
                gmin[mt * 2 + slot] = hmin2u(gmin[mt * 2 + slot], tv);
                const int pt = rw * 32 + mt * 16 + slot * 8 + r0;
                tmh[(pt * 33 + t) * 8 + cw * 4 + c4] =
                    __hmin(*(__half*)&tv, *((__half*)&tv + 1));
            }

        __syncthreads();  // all warps done reading buf before overwrite
        if (t + 2 < NTIL) {
            const unsigned char* src = g_cbB + (size_t)(t + 2) * TILE_B;
            for (int c = tid; c < TILE_B / 16; c += 128)
                cp16(smem_b + buf * TILE_B + c * 16, src + c * 16);
        }
        CP_COMMIT();
    }

    // per-point partial min (this warp's 64 cols)
    float* pm = (float*)(smem + (cw ? OFF_PM1 : OFF_PM0));
#pragma unroll
    for (int s = 0; s < 4; s++) {
        unsigned g = gmin[s];
        g = hmin2u(g, __shfl_xor_sync(0xffffffffu, g, 1));
        g = hmin2u(g, __shfl_xor_sync(0xffffffffu, g, 2));
        if (c4 == 0)
            pm[rw * 32 + (s >> 1) * 16 + (s & 1) * 8 + r0] = fminf(h2lo(g), h2hi(g));
    }
    __syncthreads();

    // recovery + exact refine, warp per point (16 points per warp)
    const float* pm0 = (const float*)(smem + OFF_PM0);
    const float* pm1 = (const float*)(smem + OFF_PM1);
    const uint4* tm4 = (const uint4*)(smem + OFF_TM);
    for (int ii = 0; ii < 16; ii++) {
        const int pl = w * 16 + ii;
        const int gpt = blockIdx.x * PTS + pl;
        const float th = fminf(pm0[pl], pm1[pl]) + MARGIN;

        float2 xv2 = ((const float2*)(x + (size_t)gpt * DIM))[lane];
        float xsq = fmaf(xv2.x, xv2.x, xv2.y * xv2.y);
#pragma unroll
        for (int o = 1; o <= 16; o <<= 1) xsq += __shfl_xor_sync(0xffffffffu, xsq, o);

        uint4 e = tm4[pl * 33 + lane];  // tile = lane; 8 fp16 subset mins
        unsigned m8 = 0;
        if (h2lo(e.x) < th) m8 |= 1u;
        if (h2hi(e.x) < th) m8 |= 2u;
        if (h2lo(e.y) < th) m8 |= 4u;
        if (h2hi(e.y) < th) m8 |= 8u;
        if (h2lo(e.z) < th) m8 |= 16u;
        if (h2hi(e.z) < th) m8 |= 32u;
        if (h2lo(e.w) < th) m8 |= 64u;
        if (h2hi(e.w) < th) m8 |= 128u;

        float bd = 3.4e38f;
        int bi = 0x7FFFFFFF;
        unsigned hitb = __ballot_sync(0xffffffffu, m8 != 0);
        while (hitb) {
            const int src = __ffs(hitb) - 1;
            hitb &= hitb - 1;
            unsigned m = __shfl_sync(0xffffffffu, m8, src);
            for (int sh = 0; sh < 8; sh++) {
                if (!(m & (1u << sh))) continue;
                // subset sh = colhalf*4 + c4s: codes src*128 + colhalf*64 + j*8 + 2*c4s + h
                const int code = src * 128 + (sh >> 2) * 64 + (lane >> 2) * 8 +
                                 2 * (sh & 3) + ((lane >> 1) & 1);
                const int part = lane & 1;
                const float4* xr = (const float4*)(x + (size_t)gpt * DIM) + part * 8;
                const float4* cr = (const float4*)(codebook + (size_t)code * DIM) + part * 8;
                float dot = 0.0f;
#pragma unroll
                for (int j = 0; j < 8; j++) {
                    float4 xa = xr[j], ca = cr[j];
                    dot = fmaf(xa.x, ca.x, dot);
                    dot = fmaf(xa.y, ca.y, dot);
                    dot = fmaf(xa.z, ca.z, dot);
                    dot = fmaf(xa.w, ca.w, dot);
                }
                dot += __shfl_xor_sync(0xffffffffu, dot, 1);
                float dd = fmaf(-2.0f, dot, xsq) + g_csq[code];
                int wi = code;
#pragma unroll
                for (int o = 2; o <= 16; o <<= 1) {
                    float od = __shfl_xor_sync(0xffffffffu, dd, o);
                    int oi = __shfl_xor_sync(0xffffffffu, wi, o);
                    if (od < dd || (od == dd && oi < wi)) { dd = od; wi = oi; }
                }
                if (dd < bd || (dd == bd && wi < bi)) { bd = dd; bi = wi; }
            }
        }

        if (lane == 0) o_idx[gpt] = (float)bi;
        ((float2*)(o_quant + (size_t)gpt * DIM))[lane] =
            ((const float2*)(codebook + (size_t)bi * DIM))[lane];
        if (lane == 0) atomicAdd(&g_counts[bi], 1.0f);
        atomicAdd(&g_embed[(size_t)bi * DIM + 2 * lane], xv2.x);
        atomicAdd(&g_embed[(size_t)bi * DIM + 2 * lane + 1], xv2.y);
    }
}

__global__ void finalize1_kernel(const float* __restrict__ cluster_size,
                                 float* __restrict__ o_cs) {
    __shared__ float warpsum[32];
    __shared__ float s_n;
    float local = 0.0f;
    for (int k = threadIdx.x; k < NCODES; k += blockDim.x) {
        float ncs = DECAY_F * cluster_size[k] + OMD_F * g_counts[k];
        o_cs[k] = ncs;
        g_ncs[k] = ncs;
        local += ncs;
    }
#pragma unroll
    for (int o = 16; o; o >>= 1) local += __shfl_down_sync(0xffffffffu, local, o);
    if ((threadIdx.x & 31) == 0) warpsum[threadIdx.x >> 5] = local;
    __syncthreads();
    if (threadIdx.x < 32) {
        float v = (threadIdx.x < (blockDim.x >> 5)) ? warpsum[threadIdx.x] : 0.0f;
#pragma unroll
        for (int o = 16; o; o >>= 1) v += __shfl_down_sync(0xffffffffu, v, o);
        if (threadIdx.x == 0) s_n = v;
    }
    __syncthreads();
    float n = s_n;
    float denom = n + (float)NCODES * EPS_F;
    for (int k = threadIdx.x; k < NCODES; k += blockDim.x) {
        float sm = (g_ncs[k] + EPS_F) / denom * n;
        g_factor[k] = 1.0f / sm;
    }
}

__global__ void finalize2_kernel(const float* __restrict__ ema_w,
                                 float* __restrict__ o_cb,
                                 float* __restrict__ o_ema) {
    int i = blockIdx.x * blockDim.x + threadIdx.x;
    if (i >= NCODES * DIM) return;
    float e = DECAY_F * ema_w[i] + OMD_F * g_embed[i];
    o_ema[i] = e;
    o_cb[i] = e * g_factor[i >> 6];
}

extern "C" void kernel_launch(void* const* d_in, const int* in_sizes, int n_in,
                              void* d_out, int out_size) {
    const float* x            = (const float*)d_in[0];
    const float* codebook     = (const float*)d_in[1];
    const float* cluster_size = (const float*)d_in[2];
    const float* ema_w        = (const float*)d_in[3];

    float* out     = (float*)d_out;
    float* o_quant = out;
    float* o_idx   = o_quant + (size_t)NPTS * DIM;
    float* o_cb    = o_idx + NPTS;
    float* o_cs    = o_cb + (size_t)NCODES * DIM;
    float* o_ema   = o_cs + NCODES;

    static int smem_set = 0;
    if (!smem_set) {
        cudaFuncSetAttribute(vq_kernel, cudaFuncAttributeMaxDynamicSharedMemorySize, SMEM_TOTAL);
        smem_set = 1;
    }

    prep_kernel<<<(NCODES * DIM + 255) / 256, 256>>>(codebook);
    vq_kernel<<<NPTS / PTS, 128, SMEM_TOTAL>>>(x, codebook, o_quant, o_idx);
    finalize1_kernel<<<1, 1024>>>(cluster_size, o_cs);
    finalize2_kernel<<<(NCODES * DIM + 255) / 256, 256>>>(ema_w, o_cb, o_ema);
}

// round 16
// speedup vs baseline: 2.1364x; 1.0244x over previous
#include <cuda_runtime.h>
#include <cuda_fp16.h>

#define NCODES 4096
#define DIM 64
#define NPTS 65536
#define NTIL 32
#define TILE_B 16640        // 128 codes x 64 k x fp16 + 256B csq-h2
#define MARGIN 0.9f
#define PTS 64              // points per CTA
#define DECAY_F 0.99f
#define OMD_F 0.01f
#define EPS_F 1e-5f

__device__ float g_counts[NCODES];
__device__ float g_embed[NCODES * DIM];
__device__ float g_ncs[NCODES];
__device__ float g_factor[NCODES];
__device__ float g_csq[NCODES];
__device__ __align__(16) unsigned char g_cbB[NTIL * TILE_B];

#define OFF_B    0             // 2 x 16640 = 33280
#define OFF_TM   33280         // [pt64][t32 pad33] x 8 fp16 = 33792
#define OFF_PM0  67072         // 64 f32 (col-half 0 partial min)
#define OFF_PM1  67328         // 64 f32 (col-half 1 partial min)
#define SMEM_TOTAL 67584

static __device__ __forceinline__ unsigned hmin2u(unsigned a, unsigned b) {
    __half2 r = __hmin2(*(__half2*)&a, *(__half2*)&b);
    return *(unsigned*)&r;
}
static __device__ __forceinline__ unsigned hadd2u(unsigned a, unsigned b) {
    __half2 r = __hadd2(*(__half2*)&a, *(__half2*)&b);
    return *(unsigned*)&r;
}
static __device__ __forceinline__ unsigned packh2(float lo, float hi) {
    __half2 h = __floats2half2_rn(lo, hi);
    return *(unsigned*)&h;
}
static __device__ __forceinline__ float h2lo(unsigned u) { return __low2float(*(__half2*)&u); }
static __device__ __forceinline__ float h2hi(unsigned u) { return __high2float(*(__half2*)&u); }

static __device__ __forceinline__ void mmaA(unsigned& d0, unsigned& d1,
                                            const unsigned* a, unsigned b0, unsigned b1) {
    asm("mma.sync.aligned.m16n8k16.row.col.f16.f16.f16.f16 "
        "{%0,%1}, {%2,%3,%4,%5}, {%6,%7}, {%0,%1};"
        : "+r"(d0), "+r"(d1)
        : "r"(a[0]), "r"(a[1]), "r"(a[2]), "r"(a[3]), "r"(b0), "r"(b1));
}
static __device__ __forceinline__ void mmaZ(unsigned& d0, unsigned& d1,
                                            const unsigned* a, unsigned b0, unsigned b1) {
    asm("mma.sync.aligned.m16n8k16.row.col.f16.f16.f16.f16 "
        "{%0,%1}, {%2,%3,%4,%5}, {%6,%7}, {%8,%8};"
        : "=r"(d0), "=r"(d1)
        : "r"(a[0]), "r"(a[1]), "r"(a[2]), "r"(a[3]), "r"(b0), "r"(b1), "r"(0u));
}
static __device__ __forceinline__ void cp16(unsigned dst, const void* src) {
    asm volatile("cp.async.cg.shared.global [%0], [%1], 16;" :: "r"(dst), "l"(src));
}
#define CP_COMMIT() asm volatile("cp.async.commit_group;" ::: "memory")
#define CP_WAIT0()  asm volatile("cp.async.wait_group 0;" ::: "memory")

// B-fragment offset (layout validated R4..R15), ks 0..3
static __device__ __forceinline__ unsigned bfrag_off(int tile, int n, int ks, int c) {
    int nt = n >> 3, nn = n & 7;
    return (unsigned)tile * TILE_B +
           (((ks * 8 + (nt >> 1)) * 32 + (nn * 4 + ((c & 7) >> 1))) * 16) +
           (nt & 1) * 8 + (c >> 3) * 4 + (c & 1) * 2;
}

// ---- prep: B frags fp16(-2c); csq-h2 blob per tile; csq f32; zero scratch ----
__global__ void prep_kernel(const float* __restrict__ codebook) {
    int i = blockIdx.x * blockDim.x + threadIdx.x;
    if (i >= NCODES * DIM) return;
    int k = i >> 6, d = i & 63;
    int tile = k >> 7, n = k & 127;
    *(__half*)(g_cbB + bfrag_off(tile, n, d >> 4, d & 15)) =
        __float2half_rn(-2.0f * codebook[i]);
    g_embed[i] = 0.0f;
    if (d == 0) {
        const float* row = codebook + (size_t)k * DIM;
        float s = 0.0f;
#pragma unroll
        for (int j = 0; j < DIM; j++) s += row[j] * row[j];
        g_csq[k] = s;
        g_counts[k] = 0.0f;
        int nt = n >> 3, c4 = (n & 7) >> 1, half = n & 1;
        *(__half*)(g_cbB + (unsigned)tile * TILE_B + 16384 +
                   ((nt * 4 + c4) * 4) + half * 2) = __float2half_rn(s);
    }
}

// ---- main: 4 warps (2 row x 2 col), m32n64 per warp, 64 pts/CTA, 3 CTAs/SM ----
// Single-barrier pipeline: wait0 -> sync -> prefetch(t+1) -> compute(t).
__global__ void __launch_bounds__(128, 3) vq_kernel(
    const float* __restrict__ x, const float* __restrict__ codebook,
    float* __restrict__ o_quant, float* __restrict__ o_idx) {
    extern __shared__ char smem[];
    const int tid = threadIdx.x, lane = tid & 31, w = tid >> 5;
    const int rw = w >> 1, cw = w & 1;  // row-warp (32 pts), col-warp (64 codes)
    const int r0 = lane >> 2, c4 = lane & 3;

    // A fragments: 2 m-tiles (rows rw*32 + mt*16 + r0, +8)
    unsigned afr[2][4][4];
#pragma unroll
    for (int mt = 0; mt < 2; mt++) {
        const float* xr0 = x + ((size_t)blockIdx.x * PTS + rw * 32 + mt * 16 + r0) * DIM;
        const float* xr1 = xr0 + 8 * DIM;
#pragma unroll
        for (int ks = 0; ks < 4; ks++) {
            float2 a = *(const float2*)(xr0 + ks * 16 + 2 * c4);
            float2 b = *(const float2*)(xr1 + ks * 16 + 2 * c4);
            float2 c = *(const float2*)(xr0 + ks * 16 + 8 + 2 * c4);
            float2 d = *(const float2*)(xr1 + ks * 16 + 8 + 2 * c4);
            afr[mt][ks][0] = packh2(a.x, a.y);
            afr[mt][ks][1] = packh2(b.x, b.y);
            afr[mt][ks][2] = packh2(c.x, c.y);
            afr[mt][ks][3] = packh2(d.x, d.y);
        }
    }

    const unsigned smem_b = (unsigned)__cvta_generic_to_shared(smem + OFF_B);
    // prologue: tile 0 only; tile t+1 issued inside iteration t (after the barrier)
    {
        const unsigned char* src = g_cbB;
        for (int c = tid; c < TILE_B / 16; c += 128)
            cp16(smem_b + c * 16, src + c * 16);
        CP_COMMIT();
    }

    unsigned gmin[4] = {0x7BFF7BFFu, 0x7BFF7BFFu, 0x7BFF7BFFu, 0x7BFF7BFFu};
    __half* tmh = (__half*)(smem + OFF_TM);

    for (int t = 0; t < NTIL; ++t) {
        const int buf = t & 1;
        CP_WAIT0();       // this thread's tile-t chunks arrived
        __syncthreads();  // ALL chunks arrived AND all warps past tile t-1 reads

        // safe now to overwrite buf^1 (last read during t-1)
        if (t + 1 < NTIL) {
            const unsigned char* src = g_cbB + (size_t)(t + 1) * TILE_B;
            for (int c = tid; c < TILE_B / 16; c += 128)
                cp16(smem_b + (buf ^ 1) * TILE_B + c * 16, src + c * 16);
            CP_COMMIT();
        }

        const uint4* B4 = (const uint4*)(smem + OFF_B + buf * TILE_B);
        const unsigned* csq2 = (const unsigned*)(smem + OFF_B + buf * TILE_B + 16384);

        unsigned acc[2][16];  // [mt][i*2+slot], i = p*2+X, cols cw*64-rel
#pragma unroll
        for (int ks = 0; ks < 4; ks++)
#pragma unroll
            for (int p = 0; p < 4; p++) {
                uint4 b = B4[(ks * 8 + cw * 4 + p) * 32 + lane];
                if (ks == 0) {
#pragma unroll
                    for (int mt = 0; mt < 2; mt++) {
                        mmaZ(acc[mt][(p * 2 + 0) * 2], acc[mt][(p * 2 + 0) * 2 + 1],
                             afr[mt][0], b.x, b.y);
                        mmaZ(acc[mt][(p * 2 + 1) * 2], acc[mt][(p * 2 + 1) * 2 + 1],
                             afr[mt][0], b.z, b.w);
                    }
                } else {
#pragma unroll
                    for (int mt = 0; mt < 2; mt++) {
                        mmaA(acc[mt][(p * 2 + 0) * 2], acc[mt][(p * 2 + 0) * 2 + 1],
                             afr[mt][ks], b.x, b.y);
                        mmaA(acc[mt][(p * 2 + 1) * 2], acc[mt][(p * 2 + 1) * 2 + 1],
                             afr[mt][ks], b.z, b.w);
                    }
                }
            }

        // epilogue: add csq, hmin trees; subset = 16 codes {cw*64+j*8+2c4+h}
        unsigned cq[8];
#pragma unroll
        for (int j = 0; j < 8; j++) cq[j] = csq2[(cw * 8 + j) * 4 + c4];

#pragma unroll
        for (int mt = 0; mt < 2; mt++)
#pragma unroll
            for (int slot = 0; slot < 2; slot++) {
                unsigned m[4];
#pragma unroll
                for (int j = 0; j < 4; j++)
                    m[j] = hmin2u(hadd2u(acc[mt][(j + 0) * 2 + slot], cq[j]),
                                  hadd2u(acc[mt][(j + 4) * 2 + slot], cq[j + 4]));
                unsigned tv = hmin2u(hmin2u(m[0], m[1]), hmin2u(m[2], m[3]));
                gmin[mt * 2 + slot] = hmin2u(gmin[mt * 2 + slot], tv);
                const int pt = rw * 32 + mt * 16 + slot * 8 + r0;
                tmh[(pt * 33 + t) * 8 + cw * 4 + c4] =
                    __hmin(*(__half*)&tv, *((__half*)&tv + 1));
            }
        // no bottom barrier: next iteration's top barrier provides the ordering
    }

    // per-point partial min (this warp's 64 cols)
    float* pm = (float*)(smem + (cw ? OFF_PM1 : OFF_PM0));
#pragma unroll
    for (int s = 0; s < 4; s++) {
        unsigned g = gmin[s];
        g = hmin2u(g, __shfl_xor_sync(0xffffffffu, g, 1));
        g = hmin2u(g, __shfl_xor_sync(0xffffffffu, g, 2));
        if (c4 == 0)
            pm[rw * 32 + (s >> 1) * 16 + (s & 1) * 8 + r0] = fminf(h2lo(g), h2hi(g));
    }
    __syncthreads();  // tm + pm visible to all warps for refine

    // recovery + exact refine, warp per point (16 points per warp)
    const float* pm0 = (const float*)(smem + OFF_PM0);
    const float* pm1 = (const float*)(smem + OFF_PM1);
    const uint4* tm4 = (const uint4*)(smem + OFF_TM);
    for (int ii = 0; ii < 16; ii++) {
        const int pl = w * 16 + ii;
        const int gpt = blockIdx.x * PTS + pl;
        const float th = fminf(pm0[pl], pm1[pl]) + MARGIN;

        float2 xv2 = ((const float2*)(x + (size_t)gpt * DIM))[lane];
        float xsq = fmaf(xv2.x, xv2.x, xv2.y * xv2.y);
#pragma unroll
        for (int o = 1; o <= 16; o <<= 1) xsq += __shfl_xor_sync(0xffffffffu, xsq, o);

        uint4 e = tm4[pl * 33 + lane];  // tile = lane; 8 fp16 subset mins
        unsigned m8 = 0;
        if (h2lo(e.x) < th) m8 |= 1u;
        if (h2hi(e.x) < th) m8 |= 2u;
        if (h2lo(e.y) < th) m8 |= 4u;
        if (h2hi(e.y) < th) m8 |= 8u;
        if (h2lo(e.z) < th) m8 |= 16u;
        if (h2hi(e.z) < th) m8 |= 32u;
        if (h2lo(e.w) < th) m8 |= 64u;
        if (h2hi(e.w) < th) m8 |= 128u;

        float bd = 3.4e38f;
        int bi = 0x7FFFFFFF;
        unsigned hitb = __ballot_sync(0xffffffffu, m8 != 0);
        while (hitb) {
            const int src = __ffs(hitb) - 1;
            hitb &= hitb - 1;
            unsigned m = __shfl_sync(0xffffffffu, m8, src);
            for (int sh = 0; sh < 8; sh++) {
                if (!(m & (1u << sh))) continue;
                // subset sh = colhalf*4 + c4s: codes src*128 + colhalf*64 + j*8 + 2*c4s + h
                const int code = src * 128 + (sh >> 2) * 64 + (lane >> 2) * 8 +
                                 2 * (sh & 3) + ((lane >> 1) & 1);
                const int part = lane & 1;
                const float4* xr = (const float4*)(x + (size_t)gpt * DIM) + part * 8;
                const float4* cr = (const float4*)(codebook + (size_t)code * DIM) + part * 8;
                float dot = 0.0f;
#pragma unroll
                for (int j = 0; j < 8; j++) {
                    float4 xa = xr[j], ca = cr[j];
                    dot = fmaf(xa.x, ca.x, dot);
                    dot = fmaf(xa.y, ca.y, dot);
                    dot = fmaf(xa.z, ca.z, dot);
                    dot = fmaf(xa.w, ca.w, dot);
                }
                dot += __shfl_xor_sync(0xffffffffu, dot, 1);
                float dd = fmaf(-2.0f, dot, xsq) + g_csq[code];
                int wi = code;
#pragma unroll
                for (int o = 2; o <= 16; o <<= 1) {
                    float od = __shfl_xor_sync(0xffffffffu, dd, o);
                    int oi = __shfl_xor_sync(0xffffffffu, wi, o);
                    if (od < dd || (od == dd && oi < wi)) { dd = od; wi = oi; }
                }
                if (dd < bd || (dd == bd && wi < bi)) { bd = dd; bi = wi; }
            }
        }

        if (lane == 0) o_idx[gpt] = (float)bi;
        ((float2*)(o_quant + (size_t)gpt * DIM))[lane] =
            ((const float2*)(codebook + (size_t)bi * DIM))[lane];
        if (lane == 0) atomicAdd(&g_counts[bi], 1.0f);
        atomicAdd(&g_embed[(size_t)bi * DIM + 2 * lane], xv2.x);
        atomicAdd(&g_embed[(size_t)bi * DIM + 2 * lane + 1], xv2.y);
    }
}

__global__ void finalize1_kernel(const float* __restrict__ cluster_size,
                                 float* __restrict__ o_cs) {
    __shared__ float warpsum[32];
    __shared__ float s_n;
    float local = 0.0f;
    for (int k = threadIdx.x; k < NCODES; k += blockDim.x) {
        float ncs = DECAY_F * cluster_size[k] + OMD_F * g_counts[k];
        o_cs[k] = ncs;
        g_ncs[k] = ncs;
        local += ncs;
    }
#pragma unroll
    for (int o = 16; o; o >>= 1) local += __shfl_down_sync(0xffffffffu, local, o);
    if ((threadIdx.x & 31) == 0) warpsum[threadIdx.x >> 5] = local;
    __syncthreads();
    if (threadIdx.x < 32) {
        float v = (threadIdx.x < (blockDim.x >> 5)) ? warpsum[threadIdx.x] : 0.0f;
#pragma unroll
        for (int o = 16; o; o >>= 1) v += __shfl_down_sync(0xffffffffu, v, o);
        if (threadIdx.x == 0) s_n = v;
    }
    __syncthreads();
    float n = s_n;
    float denom = n + (float)NCODES * EPS_F;
    for (int k = threadIdx.x; k < NCODES; k += blockDim.x) {
        float sm = (g_ncs[k] + EPS_F) / denom * n;
        g_factor[k] = 1.0f / sm;
    }
}

__global__ void finalize2_kernel(const float* __restrict__ ema_w,
                                 float* __restrict__ o_cb,
                                 float* __restrict__ o_ema) {
    int i = blockIdx.x * blockDim.x + threadIdx.x;
    if (i >= NCODES * DIM) return;
    float e = DECAY_F * ema_w[i] + OMD_F * g_embed[i];
    o_ema[i] = e;
    o_cb[i] = e * g_factor[i >> 6];
}

extern "C" void kernel_launch(void* const* d_in, const int* in_sizes, int n_in,
                              void* d_out, int out_size) {
    const float* x            = (const float*)d_in[0];
    const float* codebook     = (const float*)d_in[1];
    const float* cluster_size = (const float*)d_in[2];
    const float* ema_w        = (const float*)d_in[3];

    float* out     = (float*)d_out;
    float* o_quant = out;
    float* o_idx   = o_quant + (size_t)NPTS * DIM;
    float* o_cb    = o_idx + NPTS;
    float* o_cs    = o_cb + (size_t)NCODES * DIM;
    float* o_ema   = o_cs + NCODES;

    static int smem_set = 0;
    if (!smem_set) {
        cudaFuncSetAttribute(vq_kernel, cudaFuncAttributeMaxDynamicSharedMemorySize, SMEM_TOTAL);
        smem_set = 1;
    }

    prep_kernel<<<(NCODES * DIM + 255) / 256, 256>>>(codebook);
    vq_kernel<<<NPTS / PTS, 128, SMEM_TOTAL>>>(x, codebook, o_quant, o_idx);
    finalize1_kernel<<<1, 1024>>>(cluster_size, o_cs);
    finalize2_kernel<<<(NCODES * DIM + 255) / 256, 256>>>(ema_w, o_cb, o_ema);
}

// round 17
// speedup vs baseline: 2.1516x; 1.0071x over previous
#include <cuda_runtime.h>
#include <cuda_fp16.h>

#define NCODES 4096
#define DIM 64
#define NPTS 65536
#define NTIL 32
#define TILE_B 16640        // 128 codes x 64 k x fp16 + 256B csq-h2
#define MARGIN 0.9f
#define PTS 64              // points per CTA
#define DECAY_F 0.99f
#define OMD_F 0.01f
#define EPS_F 1e-5f

__device__ float g_counts[NCODES];
__device__ float g_embed[NCODES * DIM];
__device__ float g_ncs[NCODES];
__device__ float g_factor[NCODES];
__device__ float g_csq[NCODES];
__device__ __align__(16) unsigned char g_cbB[NTIL * TILE_B];

#define OFF_B    0             // 2 x 16640 = 33280
#define OFF_TM   33280         // [pt64][t32 pad33] x 8 fp16 = 33792
#define OFF_PM0  67072         // 64 f32 (col-half 0 partial min)
#define OFF_PM1  67328         // 64 f32 (col-half 1 partial min)
#define SMEM_TOTAL 67584

static __device__ __forceinline__ unsigned hmin2u(unsigned a, unsigned b) {
    __half2 r = __hmin2(*(__half2*)&a, *(__half2*)&b);
    return *(unsigned*)&r;
}
static __device__ __forceinline__ unsigned packh2(float lo, float hi) {
    __half2 h = __floats2half2_rn(lo, hi);
    return *(unsigned*)&h;
}
static __device__ __forceinline__ float h2lo(unsigned u) { return __low2float(*(__half2*)&u); }
static __device__ __forceinline__ float h2hi(unsigned u) { return __high2float(*(__half2*)&u); }

static __device__ __forceinline__ void mmaA(unsigned& d0, unsigned& d1,
                                            const unsigned* a, unsigned b0, unsigned b1) {
    asm("mma.sync.aligned.m16n8k16.row.col.f16.f16.f16.f16 "
        "{%0,%1}, {%2,%3,%4,%5}, {%6,%7}, {%0,%1};"
        : "+r"(d0), "+r"(d1)
        : "r"(a[0]), "r"(a[1]), "r"(a[2]), "r"(a[3]), "r"(b0), "r"(b1));
}
// first k-step: C operand = (cq, cq) — folds csq into the accumulator for free
static __device__ __forceinline__ void mmaC(unsigned& d0, unsigned& d1,
                                            const unsigned* a, unsigned b0, unsigned b1,
                                            unsigned cq) {
    asm("mma.sync.aligned.m16n8k16.row.col.f16.f16.f16.f16 "
        "{%0,%1}, {%2,%3,%4,%5}, {%6,%7}, {%8,%8};"
        : "=r"(d0), "=r"(d1)
        : "r"(a[0]), "r"(a[1]), "r"(a[2]), "r"(a[3]), "r"(b0), "r"(b1), "r"(cq));
}
static __device__ __forceinline__ void cp16(unsigned dst, const void* src) {
    asm volatile("cp.async.cg.shared.global [%0], [%1], 16;" :: "r"(dst), "l"(src));
}
#define CP_COMMIT() asm volatile("cp.async.commit_group;" ::: "memory")
#define CP_WAIT0()  asm volatile("cp.async.wait_group 0;" ::: "memory")

// B-fragment offset (layout validated R4..R16), ks 0..3
static __device__ __forceinline__ unsigned bfrag_off(int tile, int n, int ks, int c) {
    int nt = n >> 3, nn = n & 7;
    return (unsigned)tile * TILE_B +
           (((ks * 8 + (nt >> 1)) * 32 + (nn * 4 + ((c & 7) >> 1))) * 16) +
           (nt & 1) * 8 + (c >> 3) * 4 + (c & 1) * 2;
}

// ---- prep: B frags fp16(-2c); csq-h2 blob per tile; csq f32; zero scratch ----
__global__ void prep_kernel(const float* __restrict__ codebook) {
    int i = blockIdx.x * blockDim.x + threadIdx.x;
    if (i >= NCODES * DIM) return;
    int k = i >> 6, d = i & 63;
    int tile = k >> 7, n = k & 127;
    *(__half*)(g_cbB + bfrag_off(tile, n, d >> 4, d & 15)) =
        __float2half_rn(-2.0f * codebook[i]);
    g_embed[i] = 0.0f;
    if (d == 0) {
        const float* row = codebook + (size_t)k * DIM;
        float s = 0.0f;
#pragma unroll
        for (int j = 0; j < DIM; j++) s += row[j] * row[j];
        g_csq[k] = s;
        g_counts[k] = 0.0f;
        int nt = n >> 3, c4 = (n & 7) >> 1, half = n & 1;
        *(__half*)(g_cbB + (unsigned)tile * TILE_B + 16384 +
                   ((nt * 4 + c4) * 4) + half * 2) = __float2half_rn(s);
    }
}

// ---- main: 4 warps (2 row x 2 col), m32n64 per warp, 64 pts/CTA, 3 CTAs/SM ----
// Single-barrier pipeline: wait0 -> sync -> prefetch(t+1) -> compute(t).
__global__ void __launch_bounds__(128, 3) vq_kernel(
    const float* __restrict__ x, const float* __restrict__ codebook,
    float* __restrict__ o_quant, float* __restrict__ o_idx) {
    extern __shared__ char smem[];
    const int tid = threadIdx.x, lane = tid & 31, w = tid >> 5;
    const int rw = w >> 1, cw = w & 1;  // row-warp (32 pts), col-warp (64 codes)
    const int r0 = lane >> 2, c4 = lane & 3;

    // A fragments: 2 m-tiles (rows rw*32 + mt*16 + r0, +8)
    unsigned afr[2][4][4];
#pragma unroll
    for (int mt = 0; mt < 2; mt++) {
        const float* xr0 = x + ((size_t)blockIdx.x * PTS + rw * 32 + mt * 16 + r0) * DIM;
        const float* xr1 = xr0 + 8 * DIM;
#pragma unroll
        for (int ks = 0; ks < 4; ks++) {
            float2 a = *(const float2*)(xr0 + ks * 16 + 2 * c4);
            float2 b = *(const float2*)(xr1 + ks * 16 + 2 * c4);
            float2 c = *(const float2*)(xr0 + ks * 16 + 8 + 2 * c4);
            float2 d = *(const float2*)(xr1 + ks * 16 + 8 + 2 * c4);
            afr[mt][ks][0] = packh2(a.x, a.y);
            afr[mt][ks][1] = packh2(b.x, b.y);
            afr[mt][ks][2] = packh2(c.x, c.y);
            afr[mt][ks][3] = packh2(d.x, d.y);
        }
    }

    const unsigned smem_b = (unsigned)__cvta_generic_to_shared(smem + OFF_B);
    // prologue: tile 0 only; tile t+1 issued inside iteration t (after the barrier)
    {
        const unsigned char* src = g_cbB;
        for (int c = tid; c < TILE_B / 16; c += 128)
            cp16(smem_b + c * 16, src + c * 16);
        CP_COMMIT();
    }

    unsigned gmin[4] = {0x7BFF7BFFu, 0x7BFF7BFFu, 0x7BFF7BFFu, 0x7BFF7BFFu};
    __half* tmh = (__half*)(smem + OFF_TM);

    for (int t = 0; t < NTIL; ++t) {
        const int buf = t & 1;
        CP_WAIT0();       // this thread's tile-t chunks arrived
        __syncthreads();  // ALL chunks arrived AND all warps past tile t-1 reads

        // safe now to overwrite buf^1 (last read during t-1)
        if (t + 1 < NTIL) {
            const unsigned char* src = g_cbB + (size_t)(t + 1) * TILE_B;
            for (int c = tid; c < TILE_B / 16; c += 128)
                cp16(smem_b + (buf ^ 1) * TILE_B + c * 16, src + c * 16);
            CP_COMMIT();
        }

        const uint4* B4 = (const uint4*)(smem + OFF_B + buf * TILE_B);
        const unsigned* csq2 = (const unsigned*)(smem + OFF_B + buf * TILE_B + 16384);

        // csq pairs for this warp's 8 nt-groups (needed as ks=0 C operand)
        unsigned cq[8];
#pragma unroll
        for (int j = 0; j < 8; j++) cq[j] = csq2[(cw * 8 + j) * 4 + c4];

        unsigned acc[2][16];  // [mt][i*2+slot], i = p*2+X, cols cw*64-rel
#pragma unroll
        for (int ks = 0; ks < 4; ks++)
#pragma unroll
            for (int p = 0; p < 4; p++) {
                uint4 b = B4[(ks * 8 + cw * 4 + p) * 32 + lane];
                if (ks == 0) {
#pragma unroll
                    for (int mt = 0; mt < 2; mt++) {
                        mmaC(acc[mt][(p * 2 + 0) * 2], acc[mt][(p * 2 + 0) * 2 + 1],
                             afr[mt][0], b.x, b.y, cq[p * 2 + 0]);
                        mmaC(acc[mt][(p * 2 + 1) * 2], acc[mt][(p * 2 + 1) * 2 + 1],
                             afr[mt][0], b.z, b.w, cq[p * 2 + 1]);
                    }
                } else {
#pragma unroll
                    for (int mt = 0; mt < 2; mt++) {
                        mmaA(acc[mt][(p * 2 + 0) * 2], acc[mt][(p * 2 + 0) * 2 + 1],
                             afr[mt][ks], b.x, b.y);
                        mmaA(acc[mt][(p * 2 + 1) * 2], acc[mt][(p * 2 + 1) * 2 + 1],
                             afr[mt][ks], b.z, b.w);
                    }
                }
            }

        // epilogue: pure hmin trees (csq already inside accumulators)
#pragma unroll
        for (int mt = 0; mt < 2; mt++)
#pragma unroll
            for (int slot = 0; slot < 2; slot++) {
                unsigned m[4];
#pragma unroll
                for (int j = 0; j < 4; j++)
                    m[j] = hmin2u(acc[mt][(j + 0) * 2 + slot],
                                  acc[mt][(j + 4) * 2 + slot]);
                unsigned tv = hmin2u(hmin2u(m[0], m[1]), hmin2u(m[2], m[3]));
                gmin[mt * 2 + slot] = hmin2u(gmin[mt * 2 + slot], tv);
                const int pt = rw * 32 + mt * 16 + slot * 8 + r0;
                tmh[(pt * 33 + t) * 8 + cw * 4 + c4] =
                    __hmin(*(__half*)&tv, *((__half*)&tv + 1));
            }
        // no bottom barrier: next iteration's top barrier provides the ordering
    }

    // per-point partial min (this warp's 64 cols)
    float* pm = (float*)(smem + (cw ? OFF_PM1 : OFF_PM0));
#pragma unroll
    for (int s = 0; s < 4; s++) {
        unsigned g = gmin[s];
        g = hmin2u(g, __shfl_xor_sync(0xffffffffu, g, 1));
        g = hmin2u(g, __shfl_xor_sync(0xffffffffu, g, 2));
        if (c4 == 0)
            pm[rw * 32 + (s >> 1) * 16 + (s & 1) * 8 + r0] = fminf(h2lo(g), h2hi(g));
    }
    __syncthreads();  // tm + pm visible to all warps for refine

    // recovery + exact refine, warp per point (16 points per warp)
    const float* pm0 = (const float*)(smem + OFF_PM0);
    const float* pm1 = (const float*)(smem + OFF_PM1);
    const uint4* tm4 = (const uint4*)(smem + OFF_TM);
    for (int ii = 0; ii < 16; ii++) {
        const int pl = w * 16 + ii;
        const int gpt = blockIdx.x * PTS + pl;
        const float th = fminf(pm0[pl], pm1[pl]) + MARGIN;

        float2 xv2 = ((const float2*)(x + (size_t)gpt * DIM))[lane];
        float xsq = fmaf(xv2.x, xv2.x, xv2.y * xv2.y);
#pragma unroll
        for (int o = 1; o <= 16; o <<= 1) xsq += __shfl_xor_sync(0xffffffffu, xsq, o);

        uint4 e = tm4[pl * 33 + lane];  // tile = lane; 8 fp16 subset mins
        unsigned m8 = 0;
        if (h2lo(e.x) < th) m8 |= 1u;
        if (h2hi(e.x) < th) m8 |= 2u;
        if (h2lo(e.y) < th) m8 |= 4u;
        if (h2hi(e.y) < th) m8 |= 8u;
        if (h2lo(e.z) < th) m8 |= 16u;
        if (h2hi(e.z) < th) m8 |= 32u;
        if (h2lo(e.w) < th) m8 |= 64u;
        if (h2hi(e.w) < th) m8 |= 128u;

        float bd = 3.4e38f;
        int bi = 0x7FFFFFFF;
        unsigned hitb = __ballot_sync(0xffffffffu, m8 != 0);
        while (hitb) {
            const int src = __ffs(hitb) - 1;
            hitb &= hitb - 1;
            unsigned m = __shfl_sync(0xffffffffu, m8, src);
            for (int sh = 0; sh < 8; sh++) {
                if (!(m & (1u << sh))) continue;
                // subset sh = colhalf*4 + c4s: codes src*128 + colhalf*64 + j*8 + 2*c4s + h
                const int code = src * 128 + (sh >> 2) * 64 + (lane >> 2) * 8 +
                                 2 * (sh & 3) + ((lane >> 1) & 1);
                const int part = lane & 1;
                const float4* xr = (const float4*)(x + (size_t)gpt * DIM) + part * 8;
                const float4* cr = (const float4*)(codebook + (size_t)code * DIM) + part * 8;
                float dot = 0.0f;
#pragma unroll
                for (int j = 0; j < 8; j++) {
                    float4 xa = xr[j], ca = cr[j];
                    dot = fmaf(xa.x, ca.x, dot);
                    dot = fmaf(xa.y, ca.y, dot);
                    dot = fmaf(xa.z, ca.z, dot);
                    dot = fmaf(xa.w, ca.w, dot);
                }
                dot += __shfl_xor_sync(0xffffffffu, dot, 1);
                float dd = fmaf(-2.0f, dot, xsq) + g_csq[code];
                int wi = code;
#pragma unroll
                for (int o = 2; o <= 16; o <<= 1) {
                    float od = __shfl_xor_sync(0xffffffffu, dd, o);
                    int oi = __shfl_xor_sync(0xffffffffu, wi, o);
                    if (od < dd || (od == dd && oi < wi)) { dd = od; wi = oi; }
                }
                if (dd < bd || (dd == bd && wi < bi)) { bd = dd; bi = wi; }
            }
        }

        if (lane == 0) o_idx[gpt] = (float)bi;
        ((float2*)(o_quant + (size_t)gpt * DIM))[lane] =
            ((const float2*)(codebook + (size_t)bi * DIM))[lane];
        if (lane == 0) atomicAdd(&g_counts[bi], 1.0f);
        atomicAdd(&g_embed[(size_t)bi * DIM + 2 * lane], xv2.x);
        atomicAdd(&g_embed[(size_t)bi * DIM + 2 * lane + 1], xv2.y);
    }
}

__global__ void finalize1_kernel(const float* __restrict__ cluster_size,
                                 float* __restrict__ o_cs) {
    __shared__ float warpsum[32];
    __shared__ float s_n;
    float local = 0.0f;
    for (int k = threadIdx.x; k < NCODES; k += blockDim.x) {
        float ncs = DECAY_F * cluster_size[k] + OMD_F * g_counts[k];
        o_cs[k] = ncs;
        g_ncs[k] = ncs;
        local += ncs;
    }
#pragma unroll
    for (int o = 16; o; o >>= 1) local += __shfl_down_sync(0xffffffffu, local, o);
    if ((threadIdx.x & 31) == 0) warpsum[threadIdx.x >> 5] = local;
    __syncthreads();
    if (threadIdx.x < 32) {
        float v = (threadIdx.x < (blockDim.x >> 5)) ? warpsum[threadIdx.x] : 0.0f;
#pragma unroll
        for (int o = 16; o; o >>= 1) v += __shfl_down_sync(0xffffffffu, v, o);
        if (threadIdx.x == 0) s_n = v;
    }
    __syncthreads();
    float n = s_n;
    float denom = n + (float)NCODES * EPS_F;
    for (int k = threadIdx.x; k < NCODES; k += blockDim.x) {
        float sm = (g_ncs[k] + EPS_F) / denom * n;
        g_factor[k] = 1.0f / sm;
    }
}

__global__ void finalize2_kernel(const float* __restrict__ ema_w,
                                 float* __restrict__ o_cb,
                                 float* __restrict__ o_ema) {
    int i = blockIdx.x * blockDim.x + threadIdx.x;
    if (i >= NCODES * DIM) return;
    float e = DECAY_F * ema_w[i] + OMD_F * g_embed[i];
    o_ema[i] = e;
    o_cb[i] = e * g_factor[i >> 6];
}

extern "C" void kernel_launch(void* const* d_in, const int* in_sizes, int n_in,
                              void* d_out, int out_size) {
    const float* x            = (const float*)d_in[0];
    const float* codebook     = (const float*)d_in[1];
    const float* cluster_size = (const float*)d_in[2];
    const float* ema_w        = (const float*)d_in[3];

    float* out     = (float*)d_out;
    float* o_quant = out;
    float* o_idx   = o_quant + (size_t)NPTS * DIM;
    float* o_cb    = o_idx + NPTS;
    float* o_cs    = o_cb + (size_t)NCODES * DIM;
    float* o_ema   = o_cs + NCODES;

    static int smem_set = 0;
    if (!smem_set) {
        cudaFuncSetAttribute(vq_kernel, cudaFuncAttributeMaxDynamicSharedMemorySize, SMEM_TOTAL);
        smem_set = 1;
    }

    prep_kernel<<<(NCODES * DIM + 255) / 256, 256>>>(codebook);
    vq_kernel<<<NPTS / PTS, 128, SMEM_TOTAL>>>(x, codebook, o_quant, o_idx);
    finalize1_kernel<<<1, 1024>>>(cluster_size, o_cs);
    finalize2_kernel<<<(NCODES * DIM + 255) / 256, 256>>>(ema_w, o_cb, o_ema);
}